// round 3
// baseline (speedup 1.0000x reference)
#include <cuda_runtime.h>
#include <math.h>

#define NN 100000
#define EE 500000
#define HID 128

// Scratch (allocation-free rule: __device__ globals)
__device__ float g_buf0[NN * HID];   // hw / h / node_emb
__device__ float g_buf1[NN * HID];   // agg
__device__ float g_buf2[NN * HID];   // hw2
__device__ float g_dinv[NN];
__device__ int   g_deg[NN];

// ---------------- degree / dinv ----------------
__global__ void k_deg_init(int n) {
    int i = blockIdx.x * blockDim.x + threadIdx.x;
    if (i < n) g_deg[i] = 1;               // self-loop
}

__global__ void k_deg_count(const int* __restrict__ col, int E) {
    int i = blockIdx.x * blockDim.x + threadIdx.x;
    if (i < E) atomicAdd(&g_deg[col[i]], 1);
}

__global__ void k_dinv(int n) {
    int i = blockIdx.x * blockDim.x + threadIdx.x;
    if (i < n) g_dinv[i] = rsqrtf((float)g_deg[i]);
}

// ---------------- GEMM: Y[n,128] = X[n,128] @ W[128,128] ----------------
// 256 threads = 8 warps; warp w computes row (blockIdx.x*8+w), lane handles 4 cols via float4.
__global__ void k_gemm128(const float* __restrict__ X, const float* __restrict__ W,
                          float* __restrict__ Y, int n) {
    __shared__ float xs[8][HID];
    int warp = threadIdx.x >> 5, lane = threadIdx.x & 31;
    int row0 = blockIdx.x * 8;
    for (int i = threadIdx.x; i < 8 * HID; i += 256) {
        int r = row0 + (i >> 7);
        xs[i >> 7][i & 127] = (r < n) ? X[(size_t)r * HID + (i & 127)] : 0.f;
    }
    __syncthreads();
    int row = row0 + warp;
    if (row >= n) return;
    const float4* W4 = (const float4*)W;
    float4 acc = make_float4(0.f, 0.f, 0.f, 0.f);
#pragma unroll 16
    for (int k = 0; k < HID; k++) {
        float x = xs[warp][k];
        float4 w = W4[k * 32 + lane];
        acc.x = fmaf(x, w.x, acc.x); acc.y = fmaf(x, w.y, acc.y);
        acc.z = fmaf(x, w.z, acc.z); acc.w = fmaf(x, w.w, acc.w);
    }
    ((float4*)Y)[(size_t)row * 32 + lane] = acc;
}

// ---------------- self-loop init: agg[i,k] = dinv[i]^2 * hw[i,k] ----------------
__global__ void k_selfinit(const float* __restrict__ hw, float* __restrict__ agg, int n) {
    int idx = blockIdx.x * blockDim.x + threadIdx.x;
    if (idx >= n * HID) return;
    float d = g_dinv[idx >> 7];
    agg[idx] = d * d * hw[idx];
}

// ---------------- scatter: agg[col,k] += dinv[row]*dinv[col]*hw[row,k] ----------------
__global__ void k_scatter(const float* __restrict__ hw, const int* __restrict__ row,
                          const int* __restrict__ col, float* __restrict__ agg, int E) {
    int idx = blockIdx.x * blockDim.x + threadIdx.x;
    if (idx >= E * HID) return;
    int e = idx >> 7, k = idx & 127;
    int r = row[e], c = col[e];
    float v = g_dinv[r] * g_dinv[c] * hw[r * HID + k];
    atomicAdd(&agg[c * HID + k], v);
}

// ---------------- bias (+ optional ReLU) ----------------
__global__ void k_bias_act(const float* __restrict__ in, const float* __restrict__ b,
                           float* __restrict__ out, int n, int do_relu) {
    int idx = blockIdx.x * blockDim.x + threadIdx.x;
    if (idx >= n * HID) return;
    float v = in[idx] + b[idx & 127];
    out[idx] = do_relu ? fmaxf(v, 0.f) : v;
}

// ---------------- edge MLP: warp per edge ----------------
// e1 = relu(concat(emb[row],emb[col]) @ We + be)   [128]
// h2 = relu(e1 @ Wc1 + bc1)                        [64]
// logits = h2 @ Wc2 + bc2; out = softmax[:,1] = sigmoid(l1-l0)
__global__ void k_edge_mlp(const float* __restrict__ emb,
                           const int* __restrict__ row, const int* __restrict__ col,
                           const float* __restrict__ We, const float* __restrict__ be,
                           const float* __restrict__ Wc1, const float* __restrict__ bc1,
                           const float* __restrict__ Wc2, const float* __restrict__ bc2,
                           float* __restrict__ out, int E) {
    __shared__ float ab[4][2 * HID];
    __shared__ float e1s[4][HID];
    int warp = threadIdx.x >> 5, lane = threadIdx.x & 31;
    int e = blockIdx.x * 4 + warp;
    if (e >= E) return;                      // per-warp smem only; no block sync below
    int r = row[e], c = col[e];

    const float4* er = (const float4*)(emb + (size_t)r * HID);
    const float4* ec = (const float4*)(emb + (size_t)c * HID);
    ((float4*)ab[warp])[lane]      = er[lane];
    ((float4*)ab[warp])[32 + lane] = ec[lane];
    __syncwarp();

    // layer 1: lane owns cols 4*lane..4*lane+3
    const float4* We4 = (const float4*)We;
    float4 acc = ((const float4*)be)[lane];
#pragma unroll 16
    for (int k = 0; k < 2 * HID; k++) {
        float a = ab[warp][k];
        float4 w = We4[k * 32 + lane];
        acc.x = fmaf(a, w.x, acc.x); acc.y = fmaf(a, w.y, acc.y);
        acc.z = fmaf(a, w.z, acc.z); acc.w = fmaf(a, w.w, acc.w);
    }
    acc.x = fmaxf(acc.x, 0.f); acc.y = fmaxf(acc.y, 0.f);
    acc.z = fmaxf(acc.z, 0.f); acc.w = fmaxf(acc.w, 0.f);
    ((float4*)e1s[warp])[lane] = acc;
    __syncwarp();

    // layer 2: lane owns cols 2*lane, 2*lane+1
    const float2* Wc12 = (const float2*)Wc1;
    float2 a2 = ((const float2*)bc1)[lane];
#pragma unroll 16
    for (int j = 0; j < HID; j++) {
        float v = e1s[warp][j];
        float2 w = Wc12[j * 32 + lane];
        a2.x = fmaf(v, w.x, a2.x); a2.y = fmaf(v, w.y, a2.y);
    }
    float hx = fmaxf(a2.x, 0.f), hy = fmaxf(a2.y, 0.f);

    // layer 3: lane holds h2[2*lane], h2[2*lane+1]; Wc2 row m = {w(m,0),w(m,1)}
    float4 wc = ((const float4*)Wc2)[lane];  // rows 2*lane, 2*lane+1
    float p0 = hx * wc.x + hy * wc.z;
    float p1 = hx * wc.y + hy * wc.w;
#pragma unroll
    for (int o = 16; o > 0; o >>= 1) {
        p0 += __shfl_xor_sync(0xFFFFFFFFu, p0, o);
        p1 += __shfl_xor_sync(0xFFFFFFFFu, p1, o);
    }
    if (lane == 0) {
        float l0 = p0 + bc2[0], l1 = p1 + bc2[1];
        out[e] = 1.f / (1.f + expf(l0 - l1));
    }
}

extern "C" void kernel_launch(void* const* d_in, const int* in_sizes, int n_in,
                              void* d_out, int out_size) {
    const float* x   = (const float*)d_in[0];
    const int*   ei  = (const int*)d_in[1];
    const float* W1  = (const float*)d_in[2];
    const float* b1  = (const float*)d_in[3];
    const float* W2  = (const float*)d_in[4];
    const float* b2  = (const float*)d_in[5];
    const float* We  = (const float*)d_in[6];
    const float* be  = (const float*)d_in[7];
    const float* Wc1 = (const float*)d_in[8];
    const float* bc1 = (const float*)d_in[9];
    const float* Wc2 = (const float*)d_in[10];
    const float* bc2 = (const float*)d_in[11];
    float* out = (float*)d_out;

    int n = in_sizes[0] / HID;          // 100000
    int E = in_sizes[1] / 2;            // 500000
    const int* row = ei;
    const int* col = ei + E;

    float *buf0, *buf1, *buf2;
    cudaGetSymbolAddress((void**)&buf0, g_buf0);
    cudaGetSymbolAddress((void**)&buf1, g_buf1);
    cudaGetSymbolAddress((void**)&buf2, g_buf2);

    int nodeElems = n * HID;
    int edgeElems = E * HID;
    dim3 b256(256);
    int gNode  = (n + 255) / 256;
    int gEdge  = (E + 255) / 256;
    int gNE    = (nodeElems + 255) / 256;
    int gEE128 = (edgeElems + 255) / 256;
    int gGemm  = (n + 7) / 8;
    int gMlp   = (E + 3) / 4;

    // degrees / dinv
    k_deg_init<<<gNode, b256>>>(n);
    k_deg_count<<<gEdge, b256>>>(col, E);
    k_dinv<<<gNode, b256>>>(n);

    // conv1: h = relu(agg(x@W1) + b1)
    k_gemm128<<<gGemm, b256>>>(x, W1, buf0, n);
    k_selfinit<<<gNE, b256>>>(buf0, buf1, n);
    k_scatter<<<gEE128, b256>>>(buf0, row, col, buf1, E);
    k_bias_act<<<gNE, b256>>>(buf1, b1, buf0, n, 1);

    // conv2: node_emb = agg(h@W2) + b2   (no relu)
    k_gemm128<<<gGemm, b256>>>(buf0, W2, buf2, n);
    k_selfinit<<<gNE, b256>>>(buf2, buf1, n);
    k_scatter<<<gEE128, b256>>>(buf2, row, col, buf1, E);
    k_bias_act<<<gNE, b256>>>(buf1, b2, buf0, n, 0);

    // edge MLP + binary softmax
    k_edge_mlp<<<gMlp, dim3(128)>>>(buf0, row, col, We, be, Wc1, bc1, Wc2, bc2, out, E);
}

// round 4
// speedup vs baseline: 2.9130x; 2.9130x over previous
#include <cuda_runtime.h>
#include <math.h>

#define NN 100000
#define EE 500000
#define HID 128

// Scratch (allocation-free rule: __device__ globals)
__device__ float g_buf0[NN * HID];   // hw / h / node_emb
__device__ float g_buf1[NN * HID];   // agg
__device__ float g_buf2[NN * HID];   // hw2
__device__ float g_dinv[NN];
__device__ int   g_deg[NN];

typedef unsigned long long ull;

__device__ __forceinline__ ull ffma2(ull a, ull b, ull c) {
    ull d;
    asm("fma.rn.f32x2 %0, %1, %2, %3;" : "=l"(d) : "l"(a), "l"(b), "l"(c));
    return d;
}
__device__ __forceinline__ ull pack2(float x, float y) {
    ull r;
    asm("mov.b64 %0, {%1, %2};" : "=l"(r) : "f"(x), "f"(y));
    return r;
}
__device__ __forceinline__ float2 unpack2(ull v) {
    float2 f;
    asm("mov.b64 {%0, %1}, %2;" : "=f"(f.x), "=f"(f.y) : "l"(v));
    return f;
}

// ---------------- degree / dinv ----------------
__global__ void k_deg_init(int n) {
    int i = blockIdx.x * blockDim.x + threadIdx.x;
    if (i < n) g_deg[i] = 1;               // self-loop
}
__global__ void k_deg_count(const int* __restrict__ col, int E) {
    int i = blockIdx.x * blockDim.x + threadIdx.x;
    if (i < E) atomicAdd(&g_deg[col[i]], 1);
}
__global__ void k_dinv(int n) {
    int i = blockIdx.x * blockDim.x + threadIdx.x;
    if (i < n) g_dinv[i] = rsqrtf((float)g_deg[i]);
}

// ---------------- tiled GEMM: Y[n,128] = X[n,128] @ W[128,128], fused self-loop init ----
// Block: 64 rows x 128 cols, 256 threads (ty=tid>>5 owns 8 rows as 4 pairs, tx=lane owns 4 cols).
// f32x2 accumulators pack row pairs; A tile stored transposed so pairs load as LDS.64.
__global__ __launch_bounds__(256, 2)
void k_gemm_tiled(const float* __restrict__ X, const float* __restrict__ W,
                  float* __restrict__ Y, float* __restrict__ Yself, int n) {
    __shared__ float at[32 * 66];    // A chunk transposed [k][row], pad 66
    __shared__ float ws[32 * 128];   // W chunk [k][col]
    int tid = threadIdx.x, ty = tid >> 5, tx = tid & 31;
    int r0 = blockIdx.x * 64;

    ull acc[4][4];
#pragma unroll
    for (int p = 0; p < 4; p++)
#pragma unroll
        for (int j = 0; j < 4; j++) acc[p][j] = 0ull;

    for (int kc = 0; kc < 4; kc++) {
        __syncthreads();
#pragma unroll
        for (int i = 0; i < 2; i++) {
            int fi = tid + i * 256;           // 0..511 float4
            int e = fi >> 3, pos = fi & 7;
            int rr = r0 + e; if (rr >= n) rr = n - 1;
            float4 v = *(const float4*)(X + (size_t)rr * HID + kc * 32 + pos * 4);
            at[(pos * 4 + 0) * 66 + e] = v.x;
            at[(pos * 4 + 1) * 66 + e] = v.y;
            at[(pos * 4 + 2) * 66 + e] = v.z;
            at[(pos * 4 + 3) * 66 + e] = v.w;
        }
#pragma unroll
        for (int i = 0; i < 4; i++) {
            int wi = tid + i * 256;           // 0..1023 float4
            int k = wi >> 5, cg = wi & 31;
            *(float4*)&ws[k * 128 + cg * 4] =
                *(const float4*)(W + (size_t)(kc * 32 + k) * HID + cg * 4);
        }
        __syncthreads();
#pragma unroll 4
        for (int k = 0; k < 32; k++) {
            float4 w = *(float4*)&ws[k * 128 + tx * 4];
            ull w0 = pack2(w.x, w.x), w1 = pack2(w.y, w.y);
            ull w2 = pack2(w.z, w.z), w3 = pack2(w.w, w.w);
#pragma unroll
            for (int p = 0; p < 4; p++) {
                ull a = *(ull*)&at[k * 66 + ty * 8 + p * 2];
                acc[p][0] = ffma2(a, w0, acc[p][0]);
                acc[p][1] = ffma2(a, w1, acc[p][1]);
                acc[p][2] = ffma2(a, w2, acc[p][2]);
                acc[p][3] = ffma2(a, w3, acc[p][3]);
            }
        }
    }
    // epilogue: write hw and dinv^2*hw (self-loop term)
#pragma unroll
    for (int p = 0; p < 4; p++) {
        int rbase = r0 + ty * 8 + p * 2;
#pragma unroll
        for (int d = 0; d < 2; d++) {
            int rr = rbase + d;
            if (rr < n) {
                float dv = g_dinv[rr]; float dv2 = dv * dv;
#pragma unroll
                for (int j = 0; j < 4; j++) {
                    float2 f = unpack2(acc[p][j]);
                    float v = d == 0 ? f.x : f.y;
                    Y[(size_t)rr * HID + tx * 4 + j] = v;
                    Yself[(size_t)rr * HID + tx * 4 + j] = dv2 * v;
                }
            }
        }
    }
}

// ---------------- scatter: warp per edge, vector red ----------------
__global__ void k_scatter(const float* __restrict__ hw, const int* __restrict__ row,
                          const int* __restrict__ col, float* __restrict__ agg, int E) {
    int t = blockIdx.x * blockDim.x + threadIdx.x;
    int e = t >> 5, q = t & 31;
    if (e >= E) return;
    int r = row[e], c = col[e];                 // warp-broadcast loads
    float norm = g_dinv[r] * g_dinv[c];
    float4 v = *(const float4*)(hw + (size_t)r * HID + q * 4);
    v.x *= norm; v.y *= norm; v.z *= norm; v.w *= norm;
    float* p = agg + (size_t)c * HID + q * 4;
    asm volatile("red.global.add.v4.f32 [%0], {%1, %2, %3, %4};"
                 :: "l"(p), "f"(v.x), "f"(v.y), "f"(v.z), "f"(v.w) : "memory");
}

// ---------------- bias (+ optional ReLU), float4 ----------------
__global__ void k_bias_act(const float* __restrict__ in, const float* __restrict__ b,
                           float* __restrict__ out, int n, int do_relu) {
    int idx = blockIdx.x * blockDim.x + threadIdx.x;   // over n*32 float4s
    if (idx >= n * 32) return;
    int c = (idx & 31) * 4;
    float4 v = ((const float4*)in)[idx];
    float4 bb = *(const float4*)(b + c);
    v.x += bb.x; v.y += bb.y; v.z += bb.z; v.w += bb.w;
    if (do_relu) {
        v.x = fmaxf(v.x, 0.f); v.y = fmaxf(v.y, 0.f);
        v.z = fmaxf(v.z, 0.f); v.w = fmaxf(v.w, 0.f);
    }
    ((float4*)out)[idx] = v;
}

// ---------------- fused edge MLP: 64 edges per block, tiled, f32x2 ----------------
// smem (dynamic, union):
//   [0,768):            sr[64], sc[64], wd[64]
//   phase1 @768:        at[32][66] (8448B), ws[32][128] (16384B)
//   phase2 @768:        ct[128][66] (33792B), then w2[128][64] (32768B) at 768+33792
#define MLP_SMEM 67584
__global__ __launch_bounds__(256, 2)
void k_edge_mlp(const float* __restrict__ emb,
                const int* __restrict__ row, const int* __restrict__ col,
                const float* __restrict__ We, const float* __restrict__ be,
                const float* __restrict__ Wc1, const float* __restrict__ bc1,
                const float* __restrict__ Wc2, const float* __restrict__ bc2,
                float* __restrict__ out, int E) {
    extern __shared__ char smraw[];
    int*   sr = (int*)smraw;
    int*   sc = sr + 64;
    float* wd = (float*)(sc + 64);
    float* ph1 = (float*)(smraw + 768);
    float* at = ph1;                         // [32][66]
    float* ws = ph1 + 32 * 66;               // [32][128]
    float* ct = ph1;                         // [128][66] (after phase1)
    float* w2 = (float*)(smraw + 768 + 128 * 66 * 4);   // [128][64]

    int tid = threadIdx.x, ty = tid >> 5, tx = tid & 31;
    int e0 = blockIdx.x * 64;

    if (tid < 64) {
        int e = e0 + tid; if (e >= E) e = E - 1;
        sr[tid] = row[e]; sc[tid] = col[e];
        wd[tid] = Wc2[tid * 2 + 1] - Wc2[tid * 2];
    }

    // ---- layer 1: C[64,128] = relu(concat(emb[r],emb[c]) @ We + be) ----
    ull acc[4][4];
    {
        float4 b = *(const float4*)(be + tx * 4);
        ull b0 = pack2(b.x, b.x), b1 = pack2(b.y, b.y);
        ull b2 = pack2(b.z, b.z), b3 = pack2(b.w, b.w);
#pragma unroll
        for (int p = 0; p < 4; p++) { acc[p][0] = b0; acc[p][1] = b1; acc[p][2] = b2; acc[p][3] = b3; }
    }
    for (int kc = 0; kc < 8; kc++) {
        __syncthreads();
        const int* nidx = (kc < 4) ? sr : sc;
        int koff = (kc & 3) * 32;
#pragma unroll
        for (int i = 0; i < 2; i++) {
            int fi = tid + i * 256;
            int e = fi >> 3, pos = fi & 7;
            int node = nidx[e];
            float4 v = *(const float4*)(emb + (size_t)node * HID + koff + pos * 4);
            at[(pos * 4 + 0) * 66 + e] = v.x;
            at[(pos * 4 + 1) * 66 + e] = v.y;
            at[(pos * 4 + 2) * 66 + e] = v.z;
            at[(pos * 4 + 3) * 66 + e] = v.w;
        }
#pragma unroll
        for (int i = 0; i < 4; i++) {
            int wi = tid + i * 256;
            int k = wi >> 5, cg = wi & 31;
            *(float4*)&ws[k * 128 + cg * 4] =
                *(const float4*)(We + (size_t)(kc * 32 + k) * HID + cg * 4);
        }
        __syncthreads();
#pragma unroll 4
        for (int k = 0; k < 32; k++) {
            float4 w = *(float4*)&ws[k * 128 + tx * 4];
            ull w0 = pack2(w.x, w.x), w1 = pack2(w.y, w.y);
            ull wz = pack2(w.z, w.z), w3 = pack2(w.w, w.w);
#pragma unroll
            for (int p = 0; p < 4; p++) {
                ull a = *(ull*)&at[k * 66 + ty * 8 + p * 2];
                acc[p][0] = ffma2(a, w0, acc[p][0]);
                acc[p][1] = ffma2(a, w1, acc[p][1]);
                acc[p][2] = ffma2(a, wz, acc[p][2]);
                acc[p][3] = ffma2(a, w3, acc[p][3]);
            }
        }
    }
    __syncthreads();   // everyone done with at/ws -> reuse region as ct

    // store relu(C) transposed: ct[col][edge]
#pragma unroll
    for (int p = 0; p < 4; p++) {
        int e = ty * 8 + p * 2;
#pragma unroll
        for (int j = 0; j < 4; j++) {
            float2 f = unpack2(acc[p][j]);
            int c = tx * 4 + j;
            ct[c * 66 + e]     = fmaxf(f.x, 0.f);
            ct[c * 66 + e + 1] = fmaxf(f.y, 0.f);
        }
    }
    // load Wc1 [128][64]
#pragma unroll
    for (int i = 0; i < 8; i++) {
        int wi = tid + i * 256;        // 0..2047 float4
        int k = wi >> 4, cg = wi & 15;
        *(float4*)&w2[k * 64 + cg * 4] = *(const float4*)(Wc1 + (size_t)k * 64 + cg * 4);
    }
    __syncthreads();

    // ---- layer 2: H2[64,64] = relu(C @ Wc1 + bc1), cols tx*2, tx*2+1 ----
    ull a2[4][2];
    {
        float2 b = *(const float2*)(bc1 + tx * 2);
        ull b0 = pack2(b.x, b.x), b1 = pack2(b.y, b.y);
#pragma unroll
        for (int p = 0; p < 4; p++) { a2[p][0] = b0; a2[p][1] = b1; }
    }
#pragma unroll 4
    for (int k = 0; k < 128; k++) {
        float2 w = *(float2*)&w2[k * 64 + tx * 2];
        ull w0 = pack2(w.x, w.x), w1 = pack2(w.y, w.y);
#pragma unroll
        for (int p = 0; p < 4; p++) {
            ull a = *(ull*)&ct[k * 66 + ty * 8 + p * 2];
            a2[p][0] = ffma2(a, w0, a2[p][0]);
            a2[p][1] = ffma2(a, w1, a2[p][1]);
        }
    }

    // ---- layer 3 + softmax[:,1]: logit diff = sum_c h2[c]*wd[c] + bd ----
    float w0d = wd[tx * 2], w1d = wd[tx * 2 + 1];
    float bd = bc2[1] - bc2[0];
#pragma unroll
    for (int p = 0; p < 4; p++) {
        float2 h0 = unpack2(a2[p][0]);
        float2 h1 = unpack2(a2[p][1]);
        float pe0 = fmaxf(h0.x, 0.f) * w0d + fmaxf(h1.x, 0.f) * w1d;
        float pe1 = fmaxf(h0.y, 0.f) * w0d + fmaxf(h1.y, 0.f) * w1d;
#pragma unroll
        for (int o = 16; o > 0; o >>= 1) {
            pe0 += __shfl_xor_sync(0xFFFFFFFFu, pe0, o);
            pe1 += __shfl_xor_sync(0xFFFFFFFFu, pe1, o);
        }
        if (tx == 0) {
            int e = e0 + ty * 8 + p * 2;
            if (e < E)     out[e]     = 1.f / (1.f + expf(-(pe0 + bd)));
            if (e + 1 < E) out[e + 1] = 1.f / (1.f + expf(-(pe1 + bd)));
        }
    }
}

extern "C" void kernel_launch(void* const* d_in, const int* in_sizes, int n_in,
                              void* d_out, int out_size) {
    const float* x   = (const float*)d_in[0];
    const int*   ei  = (const int*)d_in[1];
    const float* W1  = (const float*)d_in[2];
    const float* b1  = (const float*)d_in[3];
    const float* W2  = (const float*)d_in[4];
    const float* b2  = (const float*)d_in[5];
    const float* We  = (const float*)d_in[6];
    const float* be  = (const float*)d_in[7];
    const float* Wc1 = (const float*)d_in[8];
    const float* bc1 = (const float*)d_in[9];
    const float* Wc2 = (const float*)d_in[10];
    const float* bc2 = (const float*)d_in[11];
    float* out = (float*)d_out;

    int n = in_sizes[0] / HID;          // 100000
    int E = in_sizes[1] / 2;            // 500000
    const int* row = ei;
    const int* col = ei + E;

    float *buf0, *buf1, *buf2;
    cudaGetSymbolAddress((void**)&buf0, g_buf0);
    cudaGetSymbolAddress((void**)&buf1, g_buf1);
    cudaGetSymbolAddress((void**)&buf2, g_buf2);

    static int smem_set = 0;
    if (!smem_set) {
        cudaFuncSetAttribute(k_edge_mlp, cudaFuncAttributeMaxDynamicSharedMemorySize, MLP_SMEM);
        smem_set = 1;
    }

    dim3 b256(256);
    int gNode  = (n + 255) / 256;
    int gEdge  = (E + 255) / 256;
    int gB     = (n * 32 + 255) / 256;            // float4 elementwise
    int gScat  = (E * 32 + 255) / 256;            // warp per edge
    int gGemm  = (n + 63) / 64;
    int gMlp   = (E + 63) / 64;

    // degrees / dinv
    k_deg_init<<<gNode, b256>>>(n);
    k_deg_count<<<gEdge, b256>>>(col, E);
    k_dinv<<<gNode, b256>>>(n);

    // conv1: h = relu(agg(x@W1) + b1)
    k_gemm_tiled<<<gGemm, b256>>>(x, W1, buf0, buf1, n);     // buf0=hw, buf1=dinv^2*hw
    k_scatter<<<gScat, b256>>>(buf0, row, col, buf1, E);
    k_bias_act<<<gB, b256>>>(buf1, b1, buf0, n, 1);

    // conv2: node_emb = agg(h@W2) + b2   (no relu)
    k_gemm_tiled<<<gGemm, b256>>>(buf0, W2, buf2, buf1, n);
    k_scatter<<<gScat, b256>>>(buf2, row, col, buf1, E);
    k_bias_act<<<gB, b256>>>(buf1, b2, buf0, n, 0);

    // fused edge MLP + binary softmax
    k_edge_mlp<<<gMlp, b256, MLP_SMEM>>>(buf0, row, col, We, be, Wc1, bc1, Wc2, bc2, out, E);
}

// round 5
// speedup vs baseline: 4.8112x; 1.6516x over previous
#include <cuda_runtime.h>
#include <math.h>

#define NN 100000
#define EE 500000
#define HID 128

// Scratch (allocation-free rule: __device__ globals)
__device__ float g_buf0[NN * HID];
__device__ float g_buf1[NN * HID];
__device__ float g_buf2[NN * HID];
__device__ float g_bufP[NN * 256];   // P = emb @ [We_top | We_bot]
__device__ float g_dinv[NN];
__device__ int   g_deg[NN];

typedef unsigned long long ull;

__device__ __forceinline__ ull ffma2(ull a, ull b, ull c) {
    ull d;
    asm("fma.rn.f32x2 %0, %1, %2, %3;" : "=l"(d) : "l"(a), "l"(b), "l"(c));
    return d;
}
__device__ __forceinline__ ull pack2(float x, float y) {
    ull r;
    asm("mov.b64 %0, {%1, %2};" : "=l"(r) : "f"(x), "f"(y));
    return r;
}
__device__ __forceinline__ float2 unpack2(ull v) {
    float2 f;
    asm("mov.b64 {%0, %1}, %2;" : "=f"(f.x), "=f"(f.y) : "l"(v));
    return f;
}

// ---------------- degree / dinv ----------------
__global__ void k_deg_init(int n) {
    int i = blockIdx.x * blockDim.x + threadIdx.x;
    if (i < n) g_deg[i] = 1;               // self-loop
}
__global__ void k_deg_count(const int* __restrict__ col, int E) {
    int i = blockIdx.x * blockDim.x + threadIdx.x;
    if (i < E) atomicAdd(&g_deg[col[i]], 1);
}
__global__ void k_dinv(int n) {
    int i = blockIdx.x * blockDim.x + threadIdx.x;
    if (i < n) g_dinv[i] = rsqrtf((float)g_deg[i]);
}

// ---------------- tiled GEMM with fused A-transform and fused self-loop epilogue ----
// Y[r, yColOff + c] = transform(X)[r,:] @ W[wRowOff:wRowOff+128, :]
// transform: mode 0 = X, mode 1 = relu(X + bias), mode 2 = X + bias
// If Yself != null: Yself[r,c] = dinv[r]^2 * result (self-loop term of GCN agg).
// Block: 64 rows x 128 cols, 256 threads; f32x2 accumulators pack row pairs.
__global__ __launch_bounds__(256, 2)
void k_gemm_tiled(const float* __restrict__ X, const float* __restrict__ bias, int mode,
                  const float* __restrict__ W, int wRowOff,
                  float* __restrict__ Y, int yLd, int yColOff,
                  float* __restrict__ Yself, int n) {
    __shared__ float at[32 * 66];    // A chunk transposed [k][row], pad 66
    __shared__ float ws[32 * 128];   // W chunk [k][col]
    int tid = threadIdx.x, ty = tid >> 5, tx = tid & 31;
    int r0 = blockIdx.x * 64;

    ull acc[4][4];
#pragma unroll
    for (int p = 0; p < 4; p++)
#pragma unroll
        for (int j = 0; j < 4; j++) acc[p][j] = 0ull;

    for (int kc = 0; kc < 4; kc++) {
        __syncthreads();
#pragma unroll
        for (int i = 0; i < 2; i++) {
            int fi = tid + i * 256;           // 0..511 float4
            int e = fi >> 3, pos = fi & 7;
            int rr = r0 + e; if (rr >= n) rr = n - 1;
            float4 v = *(const float4*)(X + (size_t)rr * HID + kc * 32 + pos * 4);
            if (mode) {
                float4 b = *(const float4*)(bias + kc * 32 + pos * 4);
                v.x += b.x; v.y += b.y; v.z += b.z; v.w += b.w;
                if (mode == 1) {
                    v.x = fmaxf(v.x, 0.f); v.y = fmaxf(v.y, 0.f);
                    v.z = fmaxf(v.z, 0.f); v.w = fmaxf(v.w, 0.f);
                }
            }
            at[(pos * 4 + 0) * 66 + e] = v.x;
            at[(pos * 4 + 1) * 66 + e] = v.y;
            at[(pos * 4 + 2) * 66 + e] = v.z;
            at[(pos * 4 + 3) * 66 + e] = v.w;
        }
#pragma unroll
        for (int i = 0; i < 4; i++) {
            int wi = tid + i * 256;           // 0..1023 float4
            int k = wi >> 5, cg = wi & 31;
            *(float4*)&ws[k * 128 + cg * 4] =
                *(const float4*)(W + (size_t)(wRowOff + kc * 32 + k) * HID + cg * 4);
        }
        __syncthreads();
#pragma unroll 4
        for (int k = 0; k < 32; k++) {
            float4 w = *(float4*)&ws[k * 128 + tx * 4];
            ull w0 = pack2(w.x, w.x), w1 = pack2(w.y, w.y);
            ull w2 = pack2(w.z, w.z), w3 = pack2(w.w, w.w);
#pragma unroll
            for (int p = 0; p < 4; p++) {
                ull a = *(ull*)&at[k * 66 + ty * 8 + p * 2];
                acc[p][0] = ffma2(a, w0, acc[p][0]);
                acc[p][1] = ffma2(a, w1, acc[p][1]);
                acc[p][2] = ffma2(a, w2, acc[p][2]);
                acc[p][3] = ffma2(a, w3, acc[p][3]);
            }
        }
    }
#pragma unroll
    for (int p = 0; p < 4; p++) {
        int rbase = r0 + ty * 8 + p * 2;
#pragma unroll
        for (int d = 0; d < 2; d++) {
            int rr = rbase + d;
            if (rr < n) {
                float dv2 = 0.f;
                if (Yself) { float dv = g_dinv[rr]; dv2 = dv * dv; }
#pragma unroll
                for (int j = 0; j < 4; j++) {
                    float2 f = unpack2(acc[p][j]);
                    float v = d == 0 ? f.x : f.y;
                    Y[(size_t)rr * yLd + yColOff + tx * 4 + j] = v;
                    if (Yself) Yself[(size_t)rr * HID + tx * 4 + j] = dv2 * v;
                }
            }
        }
    }
}

// ---------------- scatter: warp per edge, vector red ----------------
__global__ void k_scatter(const float* __restrict__ hw, const int* __restrict__ row,
                          const int* __restrict__ col, float* __restrict__ agg, int E) {
    int t = blockIdx.x * blockDim.x + threadIdx.x;
    int e = t >> 5, q = t & 31;
    if (e >= E) return;
    int r = row[e], c = col[e];                 // warp-broadcast loads
    float norm = g_dinv[r] * g_dinv[c];
    float4 v = *(const float4*)(hw + (size_t)r * HID + q * 4);
    v.x *= norm; v.y *= norm; v.z *= norm; v.w *= norm;
    float* p = agg + (size_t)c * HID + q * 4;
    asm volatile("red.global.add.v4.f32 [%0], {%1, %2, %3, %4};"
                 :: "l"(p), "f"(v.x), "f"(v.y), "f"(v.z), "f"(v.w) : "memory");
}

// ---------------- edge kernel: gather-add-relu (factorized layer 1) + layer2 + layer3 ----
// e1[e] = relu(P_top[r_e] + P_bot[c_e] + be)   (P = emb @ [We_top|We_bot] precomputed)
// h2 = relu(e1 @ Wc1 + bc1);  out = sigmoid((h2@Wc2)[1]-(...)[0] + bd)
// smem: sr[64], sc[64], wd[64] (768B) | ct[128][66] (33792B) | w2[128][64] (32768B)
#define MLP2_SMEM (768 + 128 * 66 * 4 + 128 * 64 * 4)
__global__ __launch_bounds__(256, 3)
void k_edge_mlp2(const float* __restrict__ P,
                 const int* __restrict__ row, const int* __restrict__ col,
                 const float* __restrict__ be,
                 const float* __restrict__ Wc1, const float* __restrict__ bc1,
                 const float* __restrict__ Wc2, const float* __restrict__ bc2,
                 float* __restrict__ out, int E) {
    extern __shared__ char smraw[];
    int*   sr = (int*)smraw;
    int*   sc = sr + 64;
    float* wd = (float*)(sc + 64);
    float* ct = (float*)(smraw + 768);       // [128][66], e1 transposed
    float* w2 = ct + 128 * 66;               // Wc1 [128][64]

    int tid = threadIdx.x, ty = tid >> 5, tx = tid & 31;
    int e0 = blockIdx.x * 64;

    if (tid < 64) {
        int e = e0 + tid; if (e >= E) e = E - 1;
        sr[tid] = row[e]; sc[tid] = col[e];
        wd[tid] = Wc2[tid * 2 + 1] - Wc2[tid * 2];
    }
#pragma unroll
    for (int i = 0; i < 8; i++) {
        int wi = tid + i * 256;              // 0..2047 float4
        int k = wi >> 4, cg = wi & 15;
        *(float4*)&w2[k * 64 + cg * 4] = *(const float4*)(Wc1 + (size_t)k * 64 + cg * 4);
    }
    __syncthreads();

    // gather + add + bias + relu, store transposed ct[col][edge]
#pragma unroll
    for (int i = 0; i < 8; i++) {
        int fi = tid + i * 256;              // 0..2047 float4 (64 edges x 32 f4)
        int e = fi >> 5, pos = fi & 31;
        const float4* pt = (const float4*)(P + (size_t)sr[e] * 256);
        const float4* pb = (const float4*)(P + (size_t)sc[e] * 256 + 128);
        float4 v = pt[pos], u = pb[pos];
        float4 b = ((const float4*)be)[pos];
        v.x = fmaxf(v.x + u.x + b.x, 0.f);
        v.y = fmaxf(v.y + u.y + b.y, 0.f);
        v.z = fmaxf(v.z + u.z + b.z, 0.f);
        v.w = fmaxf(v.w + u.w + b.w, 0.f);
        ct[(pos * 4 + 0) * 66 + e] = v.x;
        ct[(pos * 4 + 1) * 66 + e] = v.y;
        ct[(pos * 4 + 2) * 66 + e] = v.z;
        ct[(pos * 4 + 3) * 66 + e] = v.w;
    }
    __syncthreads();

    // layer 2: H2[64,64] = relu(e1 @ Wc1 + bc1); lane owns cols tx*2, tx*2+1
    ull a2[4][2];
    {
        float2 b = *(const float2*)(bc1 + tx * 2);
        ull b0 = pack2(b.x, b.x), b1 = pack2(b.y, b.y);
#pragma unroll
        for (int p = 0; p < 4; p++) { a2[p][0] = b0; a2[p][1] = b1; }
    }
#pragma unroll 4
    for (int k = 0; k < 128; k++) {
        float2 w = *(float2*)&w2[k * 64 + tx * 2];
        ull w0 = pack2(w.x, w.x), w1 = pack2(w.y, w.y);
#pragma unroll
        for (int p = 0; p < 4; p++) {
            ull a = *(ull*)&ct[k * 66 + ty * 8 + p * 2];
            a2[p][0] = ffma2(a, w0, a2[p][0]);
            a2[p][1] = ffma2(a, w1, a2[p][1]);
        }
    }

    // layer 3 + softmax[:,1]
    float w0d = wd[tx * 2], w1d = wd[tx * 2 + 1];
    float bd = bc2[1] - bc2[0];
#pragma unroll
    for (int p = 0; p < 4; p++) {
        float2 h0 = unpack2(a2[p][0]);
        float2 h1 = unpack2(a2[p][1]);
        float pe0 = fmaxf(h0.x, 0.f) * w0d + fmaxf(h1.x, 0.f) * w1d;
        float pe1 = fmaxf(h0.y, 0.f) * w0d + fmaxf(h1.y, 0.f) * w1d;
#pragma unroll
        for (int o = 16; o > 0; o >>= 1) {
            pe0 += __shfl_xor_sync(0xFFFFFFFFu, pe0, o);
            pe1 += __shfl_xor_sync(0xFFFFFFFFu, pe1, o);
        }
        if (tx == 0) {
            int e = e0 + ty * 8 + p * 2;
            if (e < E)     out[e]     = 1.f / (1.f + expf(-(pe0 + bd)));
            if (e + 1 < E) out[e + 1] = 1.f / (1.f + expf(-(pe1 + bd)));
        }
    }
}

extern "C" void kernel_launch(void* const* d_in, const int* in_sizes, int n_in,
                              void* d_out, int out_size) {
    const float* x   = (const float*)d_in[0];
    const int*   ei  = (const int*)d_in[1];
    const float* W1  = (const float*)d_in[2];
    const float* b1  = (const float*)d_in[3];
    const float* W2  = (const float*)d_in[4];
    const float* b2  = (const float*)d_in[5];
    const float* We  = (const float*)d_in[6];
    const float* be  = (const float*)d_in[7];
    const float* Wc1 = (const float*)d_in[8];
    const float* bc1 = (const float*)d_in[9];
    const float* Wc2 = (const float*)d_in[10];
    const float* bc2 = (const float*)d_in[11];
    float* out = (float*)d_out;

    int n = in_sizes[0] / HID;          // 100000
    int E = in_sizes[1] / 2;            // 500000
    const int* row = ei;
    const int* col = ei + E;

    float *buf0, *buf1, *buf2, *bufP;
    cudaGetSymbolAddress((void**)&buf0, g_buf0);
    cudaGetSymbolAddress((void**)&buf1, g_buf1);
    cudaGetSymbolAddress((void**)&buf2, g_buf2);
    cudaGetSymbolAddress((void**)&bufP, g_bufP);

    static int smem_set = 0;
    if (!smem_set) {
        cudaFuncSetAttribute(k_edge_mlp2, cudaFuncAttributeMaxDynamicSharedMemorySize, MLP2_SMEM);
        smem_set = 1;
    }

    dim3 b256(256);
    int gNode  = (n + 255) / 256;
    int gEdge  = (E + 255) / 256;
    int gScat  = (E * 32 + 255) / 256;
    int gGemm  = (n + 63) / 64;
    int gMlp   = (E + 63) / 64;

    // degrees / dinv
    k_deg_init<<<gNode, b256>>>(n);
    k_deg_count<<<gEdge, b256>>>(col, E);
    k_dinv<<<gNode, b256>>>(n);

    // conv1: hw1 = x@W1 (buf0), agg1 seeded with self-loop term (buf1)
    k_gemm_tiled<<<gGemm, b256>>>(x, nullptr, 0, W1, 0, buf0, HID, 0, buf1, n);
    k_scatter<<<gScat, b256>>>(buf0, row, col, buf1, E);

    // conv2: A = relu(agg1 + b1); hw2 (buf2), agg2 seeded (buf0)
    k_gemm_tiled<<<gGemm, b256>>>(buf1, b1, 1, W2, 0, buf2, HID, 0, buf0, n);
    k_scatter<<<gScat, b256>>>(buf2, row, col, buf0, E);

    // P[N,256] = (agg2 + b2) @ [We_top | We_bot]  (factorized edge-MLP layer 1)
    dim3 gP(gGemm, 2);
    k_gemm_tiled<<<dim3(gGemm,1), b256>>>(buf0, b2, 2, We, 0,   bufP, 256, 0,   nullptr, n);
    k_gemm_tiled<<<dim3(gGemm,1), b256>>>(buf0, b2, 2, We, 128, bufP, 256, 128, nullptr, n);
    (void)gP;

    // edge kernel: gather-add-relu + layer2 + layer3 + softmax[:,1]
    k_edge_mlp2<<<gMlp, b256, MLP2_SMEM>>>(bufP, row, col, be, Wc1, bc1, Wc2, bc2, out, E);
}

// round 12
// speedup vs baseline: 6.8223x; 1.4180x over previous
#include <cuda_runtime.h>
#include <cuda_bf16.h>
#include <math.h>

#define NN 100000
#define EE 500000
#define HID 128

// ---------------- scratch (allocation-free rule: __device__ globals) ----------------
__device__ float g_buf0[NN * HID];
__device__ float g_buf1[NN * HID];
__device__ float g_buf2[NN * HID];
__device__ float g_bufP[NN * 256];
__device__ float g_dinv[NN];
__device__ int   g_deg[NN];

// bf16 hi/lo transposed weight images, plain row-major Wt[n][k]
__device__ __nv_bfloat16 g_w1t_h[16384],  g_w1t_l[16384];
__device__ __nv_bfloat16 g_w2t_h[16384],  g_w2t_l[16384];
__device__ __nv_bfloat16 g_wet_h[32768],  g_wet_l[32768];    // two 128x128 halves of We
__device__ __nv_bfloat16 g_wc1t_h[8192],  g_wc1t_l[8192];    // Wt[64][128]

// smem layout constants (bf16 tiles padded to 136 elems/row = 272B: LDSM conflict-free)
#define AH_OFF 0
#define AL_OFF 34816
#define WH_OFF 69632
#define WL_OFF 104448
#define GEMM_SMEM 139264

#define EWH_OFF 69632
#define EWL_OFF 87040
#define ESR_OFF 104448
#define ESC_OFF 104960
#define EWD_OFF 105472
#define EBC_OFF 105728
#define EAC_OFF 105984
#define EDGE_SMEM 106496

// ---------------- PTX helpers (base ISA: ldmatrix + mma.sync, sm_80+) ----------------
__device__ __forceinline__ unsigned smem_u32(const void* p) {
    unsigned a;
    asm("{ .reg .u64 t; cvta.to.shared.u64 t, %1; cvt.u32.u64 %0, t; }" : "=r"(a) : "l"(p));
    return a;
}
__device__ __forceinline__ void ldsm4(unsigned* r, unsigned addr) {
    asm volatile("ldmatrix.sync.aligned.m8n8.x4.shared.b16 {%0,%1,%2,%3}, [%4];"
                 : "=r"(r[0]), "=r"(r[1]), "=r"(r[2]), "=r"(r[3]) : "r"(addr));
}
__device__ __forceinline__ void mma16816(float* d, const unsigned* a, unsigned b0, unsigned b1) {
    asm volatile("mma.sync.aligned.m16n8k16.row.col.f32.bf16.bf16.f32 "
                 "{%0,%1,%2,%3}, {%4,%5,%6,%7}, {%8,%9}, {%0,%1,%2,%3};"
                 : "+f"(d[0]), "+f"(d[1]), "+f"(d[2]), "+f"(d[3])
                 : "r"(a[0]), "r"(a[1]), "r"(a[2]), "r"(a[3]), "r"(b0), "r"(b1));
}
__device__ __forceinline__ void split_store(char* p, unsigned offH, unsigned offL, float4 v) {
    __nv_bfloat16 h0 = __float2bfloat16(v.x), h1 = __float2bfloat16(v.y);
    __nv_bfloat16 h2 = __float2bfloat16(v.z), h3 = __float2bfloat16(v.w);
    __nv_bfloat16 l0 = __float2bfloat16(v.x - __bfloat162float(h0));
    __nv_bfloat16 l1 = __float2bfloat16(v.y - __bfloat162float(h1));
    __nv_bfloat16 l2 = __float2bfloat16(v.z - __bfloat162float(h2));
    __nv_bfloat16 l3 = __float2bfloat16(v.w - __bfloat162float(h3));
    unsigned hp0 = ((unsigned)__bfloat16_as_ushort(h1) << 16) | __bfloat16_as_ushort(h0);
    unsigned hp1 = ((unsigned)__bfloat16_as_ushort(h3) << 16) | __bfloat16_as_ushort(h2);
    unsigned lp0 = ((unsigned)__bfloat16_as_ushort(l1) << 16) | __bfloat16_as_ushort(l0);
    unsigned lp1 = ((unsigned)__bfloat16_as_ushort(l3) << 16) | __bfloat16_as_ushort(l2);
    *(uint2*)(p + offH) = make_uint2(hp0, hp1);
    *(uint2*)(p + offL) = make_uint2(lp0, lp1);
}

// ---------------- degree / dinv ----------------
__global__ void k_deg_init(int n) {
    int i = blockIdx.x * blockDim.x + threadIdx.x;
    if (i < n) g_deg[i] = 1;               // self-loop
}
__global__ void k_deg_count(const int* __restrict__ col, int E) {
    int i = blockIdx.x * blockDim.x + threadIdx.x;
    if (i < E) atomicAdd(&g_deg[col[i]], 1);
}
__global__ void k_dinv(int n) {
    int i = blockIdx.x * blockDim.x + threadIdx.x;
    if (i < n) g_dinv[i] = rsqrtf((float)g_deg[i]);
}

// ---------------- weight prep: transpose + bf16 hi/lo split, plain [n][k] ----------------
__global__ void k_prep(const float* __restrict__ W1, const float* __restrict__ W2,
                       const float* __restrict__ We, const float* __restrict__ Wc1) {
    int idx = blockIdx.x * blockDim.x + threadIdx.x;
    const float* src; __nv_bfloat16 *dh, *dl; int n, k, off;
    if (idx < 16384)      { int t = idx;         n = t >> 7; k = t & 127; src = &W1[k * 128 + n];         dh = g_w1t_h;         dl = g_w1t_l;         off = n * 128 + k; }
    else if (idx < 32768) { int t = idx - 16384; n = t >> 7; k = t & 127; src = &W2[k * 128 + n];         dh = g_w2t_h;         dl = g_w2t_l;         off = n * 128 + k; }
    else if (idx < 49152) { int t = idx - 32768; n = t >> 7; k = t & 127; src = &We[k * 128 + n];         dh = g_wet_h;         dl = g_wet_l;         off = n * 128 + k; }
    else if (idx < 65536) { int t = idx - 49152; n = t >> 7; k = t & 127; src = &We[(128 + k) * 128 + n]; dh = g_wet_h + 16384; dl = g_wet_l + 16384; off = n * 128 + k; }
    else if (idx < 73728) { int t = idx - 65536; n = t >> 7; k = t & 127; src = &Wc1[k * 64 + n];         dh = g_wc1t_h;        dl = g_wc1t_l;        off = n * 128 + k; }
    else return;
    float v = *src;
    __nv_bfloat16 hi = __float2bfloat16(v);
    __nv_bfloat16 lo = __float2bfloat16(v - __bfloat162float(hi));
    dh[off] = hi; dl[off] = lo;
}

// ---------------- HMMA GEMM: Y[r, gy*128+c] = transform(X)[r,:] @ Wt^T (hi/lo split) ----
// mode: 0 = X, 1 = relu(X+bias), 2 = X+bias.  If Yself: Yself[r,c] = dinv[r]^2 * result.
// Block 128 rows x 128 cols, K=128 resident. 8 warps: wm=wid>>1 (m32), wn=wid&1 (n64).
__global__ __launch_bounds__(256)
void k_gemm_hmma(const float* __restrict__ X, const float* __restrict__ bias, int mode,
                 const __nv_bfloat16* __restrict__ WtH, const __nv_bfloat16* __restrict__ WtL,
                 float* __restrict__ Y, int yLd, float* __restrict__ Yself, int n) {
    extern __shared__ char p[];
    unsigned base = smem_u32(p);
    int tid = threadIdx.x, wid = tid >> 5, lane = tid & 31;
    int r0 = blockIdx.x * 128;

    // stage weights [128][136] h/l  (row = 128 bf16 = 16 x 16B chunks)
    {
        const float4* sH = (const float4*)(WtH + blockIdx.y * 16384);
        const float4* sL = (const float4*)(WtL + blockIdx.y * 16384);
#pragma unroll
        for (int i = 0; i < 8; i++) {
            int idx = tid + i * 256;                 // 0..2047
            int row = idx >> 4, seg = idx & 15;
            *(float4*)(p + WH_OFF + row * 272 + seg * 16) = sH[idx];
            *(float4*)(p + WL_OFF + row * 272 + seg * 16) = sL[idx];
        }
    }
    // stage A: transform + hi/lo split into [128][136] bf16
#pragma unroll
    for (int i = 0; i < 16; i++) {
        int fi = tid + i * 256;                      // 0..4095
        int r = fi >> 5, q = fi & 31;
        int rr = r0 + r; if (rr >= n) rr = n - 1;
        float4 v = *(const float4*)(X + (size_t)rr * HID + q * 4);
        if (mode) {
            float4 b = *(const float4*)(bias + q * 4);
            v.x += b.x; v.y += b.y; v.z += b.z; v.w += b.w;
            if (mode == 1) {
                v.x = fmaxf(v.x, 0.f); v.y = fmaxf(v.y, 0.f);
                v.z = fmaxf(v.z, 0.f); v.w = fmaxf(v.w, 0.f);
            }
        }
        split_store(p, AH_OFF + r * 272 + q * 8, AL_OFF + r * 272 + q * 8, v);
    }
    __syncthreads();

    int wm = wid >> 1, wn = wid & 1;
    int grp = lane >> 3, lr = lane & 7;
    unsigned aA = base + AH_OFF + ((wm * 32 + (grp & 1) * 8 + lr) * 136 + (grp >> 1) * 8) * 2;
    unsigned bB = base + WH_OFF + ((wn * 64 + (grp >> 1) * 8 + lr) * 136 + (grp & 1) * 8) * 2;

    float acc[2][8][4];
#pragma unroll
    for (int a = 0; a < 2; a++)
#pragma unroll
        for (int b = 0; b < 8; b++)
#pragma unroll
            for (int c = 0; c < 4; c++) acc[a][b][c] = 0.f;

#pragma unroll 2
    for (int ks = 0; ks < 8; ks++) {
        unsigned ah0[4], ah1[4], al0[4], al1[4];
        ldsm4(ah0, aA + ks * 32);
        ldsm4(ah1, aA + 4352 + ks * 32);
        ldsm4(al0, aA + 34816 + ks * 32);
        ldsm4(al1, aA + 34816 + 4352 + ks * 32);
#pragma unroll
        for (int nb2 = 0; nb2 < 4; nb2++) {
            unsigned bh[4], bl[4];
            ldsm4(bh, bB + nb2 * 4352 + ks * 32);
            ldsm4(bl, bB + 34816 + nb2 * 4352 + ks * 32);
            mma16816(acc[0][2 * nb2],     ah0, bh[0], bh[1]);
            mma16816(acc[0][2 * nb2 + 1], ah0, bh[2], bh[3]);
            mma16816(acc[1][2 * nb2],     ah1, bh[0], bh[1]);
            mma16816(acc[1][2 * nb2 + 1], ah1, bh[2], bh[3]);
            mma16816(acc[0][2 * nb2],     ah0, bl[0], bl[1]);
            mma16816(acc[0][2 * nb2 + 1], ah0, bl[2], bl[3]);
            mma16816(acc[1][2 * nb2],     ah1, bl[0], bl[1]);
            mma16816(acc[1][2 * nb2 + 1], ah1, bl[2], bl[3]);
            mma16816(acc[0][2 * nb2],     al0, bh[0], bh[1]);
            mma16816(acc[0][2 * nb2 + 1], al0, bh[2], bh[3]);
            mma16816(acc[1][2 * nb2],     al1, bh[0], bh[1]);
            mma16816(acc[1][2 * nb2 + 1], al1, bh[2], bh[3]);
        }
    }
    __syncthreads();

    // stage accumulators to smem [128][132] f32 (overwrites A region), coalesced writeout
    float* stg = (float*)p;
#pragma unroll
    for (int mf = 0; mf < 2; mf++)
#pragma unroll
        for (int nb = 0; nb < 8; nb++)
#pragma unroll
            for (int i = 0; i < 4; i++) {
                int row = wm * 32 + mf * 16 + (lane >> 2) + (i >> 1) * 8;
                int col = wn * 64 + nb * 8 + (lane & 3) * 2 + (i & 1);
                stg[row * 132 + col] = acc[mf][nb][i];
            }
    __syncthreads();
#pragma unroll
    for (int i = 0; i < 16; i++) {
        int fi = tid + i * 256;
        int r = fi >> 5, q = fi & 31;
        int rr = r0 + r;
        if (rr < n) {
            float4 v;
            v.x = stg[r * 132 + q * 4 + 0]; v.y = stg[r * 132 + q * 4 + 1];
            v.z = stg[r * 132 + q * 4 + 2]; v.w = stg[r * 132 + q * 4 + 3];
            *(float4*)(Y + (size_t)rr * yLd + blockIdx.y * 128 + q * 4) = v;
            if (Yself) {
                float dv = g_dinv[rr]; float s2 = dv * dv;
                v.x *= s2; v.y *= s2; v.z *= s2; v.w *= s2;
                *(float4*)(Yself + (size_t)rr * HID + q * 4) = v;
            }
        }
    }
}

// ---------------- scatter: warp per edge, vector red ----------------
__global__ void k_scatter(const float* __restrict__ hw, const int* __restrict__ row,
                          const int* __restrict__ col, float* __restrict__ agg, int E) {
    int t = blockIdx.x * blockDim.x + threadIdx.x;
    int e = t >> 5, q = t & 31;
    if (e >= E) return;
    int r = row[e], c = col[e];
    float norm = g_dinv[r] * g_dinv[c];
    float4 v = *(const float4*)(hw + (size_t)r * HID + q * 4);
    v.x *= norm; v.y *= norm; v.z *= norm; v.w *= norm;
    float* p = agg + (size_t)c * HID + q * 4;
    asm volatile("red.global.add.v4.f32 [%0], {%1, %2, %3, %4};"
                 :: "l"(p), "f"(v.x), "f"(v.y), "f"(v.z), "f"(v.w) : "memory");
}

// ---------------- edge kernel: gather+relu (factorized L1) -> HMMA L2 -> L3+sigmoid ----
// 128 edges/block. e1 = relu(P_top[r]+P_bot[c]+be) [128]; h2 = relu(e1@Wc1+bc1) [64];
// out = sigmoid(sum_c h2[c]*(Wc2[c,1]-Wc2[c,0]) + (bc2[1]-bc2[0]))
// 8 warps: wm=wid>>1 (32 edges), wn=wid&1 (n32).
__global__ __launch_bounds__(256)
void k_edge_hmma(const float* __restrict__ P,
                 const int* __restrict__ row, const int* __restrict__ col,
                 const float* __restrict__ be, const float* __restrict__ bc1,
                 const float* __restrict__ Wc2, const float* __restrict__ bc2,
                 float* __restrict__ out, int E) {
    extern __shared__ char p[];
    unsigned base = smem_u32(p);
    int*   sr   = (int*)(p + ESR_OFF);
    int*   sc   = (int*)(p + ESC_OFF);
    float* wdf  = (float*)(p + EWD_OFF);
    float* sbc1 = (float*)(p + EBC_OFF);
    float* eacc = (float*)(p + EAC_OFF);
    int tid = threadIdx.x, wid = tid >> 5, lane = tid & 31;
    int e0 = blockIdx.x * 128;

    if (tid < 128) {
        int e = e0 + tid; if (e >= E) e = E - 1;
        sr[tid] = row[e]; sc[tid] = col[e];
        eacc[tid] = 0.f;
    }
    if (tid < 64) {
        wdf[tid]  = Wc2[tid * 2 + 1] - Wc2[tid * 2];
        sbc1[tid] = bc1[tid];
    }
    {   // stage Wc1t [64][136] h/l  (row = 128 bf16 = 16 x 16B chunks)
        const float4* sH = (const float4*)g_wc1t_h;
        const float4* sL = (const float4*)g_wc1t_l;
#pragma unroll
        for (int i = 0; i < 4; i++) {
            int idx = tid + i * 256;                 // 0..1023
            int r = idx >> 4, seg = idx & 15;
            *(float4*)(p + EWH_OFF + r * 272 + seg * 16) = sH[idx];
            *(float4*)(p + EWL_OFF + r * 272 + seg * 16) = sL[idx];
        }
    }
    __syncthreads();   // sr/sc + eacc ready

    const float4* P4 = (const float4*)P;
#pragma unroll
    for (int i = 0; i < 16; i++) {
        int fi = tid + i * 256;
        int e = fi >> 5, q = fi & 31;
        float4 v = P4[(size_t)sr[e] * 64 + q];
        float4 u = P4[(size_t)sc[e] * 64 + 32 + q];
        float4 b = *(const float4*)(be + q * 4);
        v.x = fmaxf(v.x + u.x + b.x, 0.f);
        v.y = fmaxf(v.y + u.y + b.y, 0.f);
        v.z = fmaxf(v.z + u.z + b.z, 0.f);
        v.w = fmaxf(v.w + u.w + b.w, 0.f);
        split_store(p, AH_OFF + e * 272 + q * 8, AL_OFF + e * 272 + q * 8, v);
    }
    __syncthreads();

    int wm = wid >> 1, wn = wid & 1;
    int grp = lane >> 3, lr = lane & 7;
    unsigned aA = base + AH_OFF + ((wm * 32 + (grp & 1) * 8 + lr) * 136 + (grp >> 1) * 8) * 2;
    unsigned bB = base + EWH_OFF + ((wn * 32 + (grp >> 1) * 8 + lr) * 136 + (grp & 1) * 8) * 2;

    float acc[2][4][4];
#pragma unroll
    for (int a = 0; a < 2; a++)
#pragma unroll
        for (int b = 0; b < 4; b++)
#pragma unroll
            for (int c = 0; c < 4; c++) acc[a][b][c] = 0.f;

#pragma unroll 2
    for (int ks = 0; ks < 8; ks++) {
        unsigned ah0[4], ah1[4], al0[4], al1[4];
        ldsm4(ah0, aA + ks * 32);
        ldsm4(ah1, aA + 4352 + ks * 32);
        ldsm4(al0, aA + 34816 + ks * 32);
        ldsm4(al1, aA + 34816 + 4352 + ks * 32);
#pragma unroll
        for (int nb2 = 0; nb2 < 2; nb2++) {
            unsigned bh[4], bl[4];
            ldsm4(bh, bB + nb2 * 4352 + ks * 32);
            ldsm4(bl, bB + 17408 + nb2 * 4352 + ks * 32);
            mma16816(acc[0][2 * nb2],     ah0, bh[0], bh[1]);
            mma16816(acc[0][2 * nb2 + 1], ah0, bh[2], bh[3]);
            mma16816(acc[1][2 * nb2],     ah1, bh[0], bh[1]);
            mma16816(acc[1][2 * nb2 + 1], ah1, bh[2], bh[3]);
            mma16816(acc[0][2 * nb2],     ah0, bl[0], bl[1]);
            mma16816(acc[0][2 * nb2 + 1], ah0, bl[2], bl[3]);
            mma16816(acc[1][2 * nb2],     ah1, bl[0], bl[1]);
            mma16816(acc[1][2 * nb2 + 1], ah1, bl[2], bl[3]);
            mma16816(acc[0][2 * nb2],     al0, bh[0], bh[1]);
            mma16816(acc[0][2 * nb2 + 1], al0, bh[2], bh[3]);
            mma16816(acc[1][2 * nb2],     al1, bh[0], bh[1]);
            mma16816(acc[1][2 * nb2 + 1], al1, bh[2], bh[3]);
        }
    }

    // epilogue: h2 = relu(acc + bc1); partial dot with wdf; reduce lanes + warps
#pragma unroll
    for (int mf = 0; mf < 2; mf++) {
        float pr = 0.f, pr8 = 0.f;
#pragma unroll
        for (int nb = 0; nb < 4; nb++) {
            int c = wn * 32 + nb * 8 + (lane & 3) * 2;
            pr  += fmaxf(acc[mf][nb][0] + sbc1[c],     0.f) * wdf[c]
                 + fmaxf(acc[mf][nb][1] + sbc1[c + 1], 0.f) * wdf[c + 1];
            pr8 += fmaxf(acc[mf][nb][2] + sbc1[c],     0.f) * wdf[c]
                 + fmaxf(acc[mf][nb][3] + sbc1[c + 1], 0.f) * wdf[c + 1];
        }
#pragma unroll
        for (int o = 1; o <= 2; o <<= 1) {
            pr  += __shfl_xor_sync(0xFFFFFFFFu, pr, o);
            pr8 += __shfl_xor_sync(0xFFFFFFFFu, pr8, o);
        }
        if ((lane & 3) == 0) {
            int rl = wm * 32 + mf * 16 + (lane >> 2);
            atomicAdd(&eacc[rl], pr);
            atomicAdd(&eacc[rl + 8], pr8);
        }
    }
    __syncthreads();
    if (tid < 128) {
        int e = e0 + tid;
        float bd = bc2[1] - bc2[0];
        if (e < E) out[e] = 1.f / (1.f + expf(-(eacc[tid] + bd)));
    }
}

extern "C" void kernel_launch(void* const* d_in, const int* in_sizes, int n_in,
                              void* d_out, int out_size) {
    const float* x   = (const float*)d_in[0];
    const int*   ei  = (const int*)d_in[1];
    const float* W1  = (const float*)d_in[2];
    const float* b1  = (const float*)d_in[3];
    const float* W2  = (const float*)d_in[4];
    const float* b2  = (const float*)d_in[5];
    const float* We  = (const float*)d_in[6];
    const float* be  = (const float*)d_in[7];
    const float* Wc1 = (const float*)d_in[8];
    const float* bc1 = (const float*)d_in[9];
    const float* Wc2 = (const float*)d_in[10];
    const float* bc2 = (const float*)d_in[11];
    float* out = (float*)d_out;

    int n = in_sizes[0] / HID;          // 100000
    int E = in_sizes[1] / 2;            // 500000
    const int* row = ei;
    const int* col = ei + E;

    float *buf0, *buf1, *buf2, *bufP;
    cudaGetSymbolAddress((void**)&buf0, g_buf0);
    cudaGetSymbolAddress((void**)&buf1, g_buf1);
    cudaGetSymbolAddress((void**)&buf2, g_buf2);
    cudaGetSymbolAddress((void**)&bufP, g_bufP);
    __nv_bfloat16 *w1h, *w1l, *w2h, *w2l, *weh, *wel;
    cudaGetSymbolAddress((void**)&w1h, g_w1t_h); cudaGetSymbolAddress((void**)&w1l, g_w1t_l);
    cudaGetSymbolAddress((void**)&w2h, g_w2t_h); cudaGetSymbolAddress((void**)&w2l, g_w2t_l);
    cudaGetSymbolAddress((void**)&weh, g_wet_h); cudaGetSymbolAddress((void**)&wel, g_wet_l);

    static int inited = 0;
    if (!inited) {
        cudaFuncSetAttribute(k_gemm_hmma, cudaFuncAttributeMaxDynamicSharedMemorySize, GEMM_SMEM);
        cudaFuncSetAttribute(k_edge_hmma, cudaFuncAttributeMaxDynamicSharedMemorySize, EDGE_SMEM);
        inited = 1;
    }

    dim3 b256(256);
    int gNode = (n + 255) / 256;
    int gEdge = (E + 255) / 256;
    int gScat = (E * 32 + 255) / 256;
    int gG    = (n + 127) / 128;
    int gM    = (E + 127) / 128;

    // degrees / dinv + weight prep
    k_deg_init<<<gNode, b256>>>(n);
    k_deg_count<<<gEdge, b256>>>(col, E);
    k_dinv<<<gNode, b256>>>(n);
    k_prep<<<288, b256>>>(W1, W2, We, Wc1);

    // conv1: hw1 = x@W1 (buf0), agg seeded with self-loop (buf1)
    k_gemm_hmma<<<dim3(gG, 1), b256, GEMM_SMEM>>>(x, nullptr, 0, w1h, w1l, buf0, HID, buf1, n);
    k_scatter<<<gScat, b256>>>(buf0, row, col, buf1, E);

    // conv2: A = relu(agg1+b1); hw2 (buf2), agg2 seeded (buf0)
    k_gemm_hmma<<<dim3(gG, 1), b256, GEMM_SMEM>>>(buf1, b1, 1, w2h, w2l, buf2, HID, buf0, n);
    k_scatter<<<gScat, b256>>>(buf2, row, col, buf0, E);

    // P[N,256] = (agg2+b2) @ [We_top | We_bot]  (grid.y selects half)
    k_gemm_hmma<<<dim3(gG, 2), b256, GEMM_SMEM>>>(buf0, b2, 2, weh, wel, bufP, 256, nullptr, n);

    // edge: gather-add-relu + HMMA layer2 + layer3 + sigmoid
    k_edge_hmma<<<gM, b256, EDGE_SMEM>>>(bufP, row, col, be, bc1, Wc2, bc2, out, E);
}

// round 13
// speedup vs baseline: 7.5769x; 1.1106x over previous
#include <cuda_runtime.h>
#include <cuda_bf16.h>
#include <math.h>

#define NN 100000
#define EE 500000
#define HID 128

// ---------------- scratch (allocation-free rule: __device__ globals) ----------------
__device__ float g_buf0[NN * HID];
__device__ float g_buf1[NN * HID];
__device__ float g_buf2[NN * HID];
__device__ float g_bufP[NN * 256];
__device__ float g_dinv[NN];
__device__ int   g_deg[NN];          // invariant: zero at kernel_launch entry (reset by k_dinv)

// bf16 hi/lo transposed weight images, plain row-major Wt[n][k]
__device__ __nv_bfloat16 g_w1t_h[16384],  g_w1t_l[16384];
__device__ __nv_bfloat16 g_w2t_h[16384],  g_w2t_l[16384];
__device__ __nv_bfloat16 g_wet_h[32768],  g_wet_l[32768];    // two 128x128 halves of We
__device__ __nv_bfloat16 g_wc1t_h[8192],  g_wc1t_l[8192];    // Wt[64][128]

// GEMM smem layout: 64-row A tile (2 CTAs/SM). Rows padded to 136 bf16 = 272B.
#define AH_OFF 0
#define AL_OFF 17408
#define WH_OFF 34816
#define WL_OFF 69632
#define GEMM_SMEM 104448

// Edge kernel smem layout (128-edge A tile)
#define EAH_OFF 0
#define EAL_OFF 34816
#define EWH_OFF 69632
#define EWL_OFF 87040
#define ESR_OFF 104448
#define ESC_OFF 104960
#define EWD_OFF 105472
#define EBC_OFF 105728
#define EAC_OFF 105984
#define EDGE_SMEM 106496

// ---------------- PTX helpers (base ISA: ldmatrix + mma.sync, sm_80+) ----------------
__device__ __forceinline__ unsigned smem_u32(const void* p) {
    unsigned a;
    asm("{ .reg .u64 t; cvta.to.shared.u64 t, %1; cvt.u32.u64 %0, t; }" : "=r"(a) : "l"(p));
    return a;
}
__device__ __forceinline__ void ldsm4(unsigned* r, unsigned addr) {
    asm volatile("ldmatrix.sync.aligned.m8n8.x4.shared.b16 {%0,%1,%2,%3}, [%4];"
                 : "=r"(r[0]), "=r"(r[1]), "=r"(r[2]), "=r"(r[3]) : "r"(addr));
}
__device__ __forceinline__ void mma16816(float* d, const unsigned* a, unsigned b0, unsigned b1) {
    asm volatile("mma.sync.aligned.m16n8k16.row.col.f32.bf16.bf16.f32 "
                 "{%0,%1,%2,%3}, {%4,%5,%6,%7}, {%8,%9}, {%0,%1,%2,%3};"
                 : "+f"(d[0]), "+f"(d[1]), "+f"(d[2]), "+f"(d[3])
                 : "r"(a[0]), "r"(a[1]), "r"(a[2]), "r"(a[3]), "r"(b0), "r"(b1));
}
__device__ __forceinline__ void split_store(char* p, unsigned offH, unsigned offL, float4 v) {
    __nv_bfloat16 h0 = __float2bfloat16(v.x), h1 = __float2bfloat16(v.y);
    __nv_bfloat16 h2 = __float2bfloat16(v.z), h3 = __float2bfloat16(v.w);
    __nv_bfloat16 l0 = __float2bfloat16(v.x - __bfloat162float(h0));
    __nv_bfloat16 l1 = __float2bfloat16(v.y - __bfloat162float(h1));
    __nv_bfloat16 l2 = __float2bfloat16(v.z - __bfloat162float(h2));
    __nv_bfloat16 l3 = __float2bfloat16(v.w - __bfloat162float(h3));
    unsigned hp0 = ((unsigned)__bfloat16_as_ushort(h1) << 16) | __bfloat16_as_ushort(h0);
    unsigned hp1 = ((unsigned)__bfloat16_as_ushort(h3) << 16) | __bfloat16_as_ushort(h2);
    unsigned lp0 = ((unsigned)__bfloat16_as_ushort(l1) << 16) | __bfloat16_as_ushort(l0);
    unsigned lp1 = ((unsigned)__bfloat16_as_ushort(l3) << 16) | __bfloat16_as_ushort(l2);
    *(uint2*)(p + offH) = make_uint2(hp0, hp1);
    *(uint2*)(p + offL) = make_uint2(lp0, lp1);
}

// ---------------- degree / dinv ----------------
__global__ void k_deg_count(const int* __restrict__ col, int E) {
    int i = blockIdx.x * blockDim.x + threadIdx.x;
    if (i < E) atomicAdd(&g_deg[col[i]], 1);
}
// dinv = rsqrt(deg + 1) (self-loop folded in), then RESET deg to 0 so the
// zero-state invariant holds for the next replay (deterministic per call).
__global__ void k_dinv(int n) {
    int i = blockIdx.x * blockDim.x + threadIdx.x;
    if (i < n) { g_dinv[i] = rsqrtf((float)(g_deg[i] + 1)); g_deg[i] = 0; }
}

// ---------------- weight prep: transpose + bf16 hi/lo split, plain [n][k] ----------------
__global__ void k_prep(const float* __restrict__ W1, const float* __restrict__ W2,
                       const float* __restrict__ We, const float* __restrict__ Wc1) {
    int idx = blockIdx.x * blockDim.x + threadIdx.x;
    const float* src; __nv_bfloat16 *dh, *dl; int n, k, off;
    if (idx < 16384)      { int t = idx;         n = t >> 7; k = t & 127; src = &W1[k * 128 + n];         dh = g_w1t_h;         dl = g_w1t_l;         off = n * 128 + k; }
    else if (idx < 32768) { int t = idx - 16384; n = t >> 7; k = t & 127; src = &W2[k * 128 + n];         dh = g_w2t_h;         dl = g_w2t_l;         off = n * 128 + k; }
    else if (idx < 49152) { int t = idx - 32768; n = t >> 7; k = t & 127; src = &We[k * 128 + n];         dh = g_wet_h;         dl = g_wet_l;         off = n * 128 + k; }
    else if (idx < 65536) { int t = idx - 49152; n = t >> 7; k = t & 127; src = &We[(128 + k) * 128 + n]; dh = g_wet_h + 16384; dl = g_wet_l + 16384; off = n * 128 + k; }
    else if (idx < 73728) { int t = idx - 65536; n = t >> 7; k = t & 127; src = &Wc1[k * 64 + n];         dh = g_wc1t_h;        dl = g_wc1t_l;        off = n * 128 + k; }
    else return;
    float v = *src;
    __nv_bfloat16 hi = __float2bfloat16(v);
    __nv_bfloat16 lo = __float2bfloat16(v - __bfloat162float(hi));
    dh[off] = hi; dl[off] = lo;
}

// ---------------- HMMA GEMM: Y[r, gy*128+c] = transform(X)[r,:] @ Wt^T (hi/lo split) ----
// mode: 0 = X, 1 = relu(X+bias), 2 = X+bias.  If Yself: Yself[r,c] = dinv[r]^2 * result.
// Block 64 rows x 128 cols, K=128 resident; smem 104.4KB -> 2 CTAs/SM.
// 8 warps: wm=wid>>1 owns m16, wn=wid&1 owns n64.
__global__ __launch_bounds__(256)
void k_gemm_hmma(const float* __restrict__ X, const float* __restrict__ bias, int mode,
                 const __nv_bfloat16* __restrict__ WtH, const __nv_bfloat16* __restrict__ WtL,
                 float* __restrict__ Y, int yLd, float* __restrict__ Yself, int n) {
    extern __shared__ char p[];
    unsigned base = smem_u32(p);
    int tid = threadIdx.x, wid = tid >> 5, lane = tid & 31;
    int r0 = blockIdx.x * 64;

    // stage weights [128][136] h/l  (row = 128 bf16 = 16 x 16B chunks)
    {
        const float4* sH = (const float4*)(WtH + blockIdx.y * 16384);
        const float4* sL = (const float4*)(WtL + blockIdx.y * 16384);
#pragma unroll
        for (int i = 0; i < 8; i++) {
            int idx = tid + i * 256;                 // 0..2047
            int row = idx >> 4, seg = idx & 15;
            *(float4*)(p + WH_OFF + row * 272 + seg * 16) = sH[idx];
            *(float4*)(p + WL_OFF + row * 272 + seg * 16) = sL[idx];
        }
    }
    // stage A: transform + hi/lo split into [64][136] bf16
#pragma unroll
    for (int i = 0; i < 8; i++) {
        int fi = tid + i * 256;                      // 0..2047
        int r = fi >> 5, q = fi & 31;
        int rr = r0 + r; if (rr >= n) rr = n - 1;
        float4 v = *(const float4*)(X + (size_t)rr * HID + q * 4);
        if (mode) {
            float4 b = *(const float4*)(bias + q * 4);
            v.x += b.x; v.y += b.y; v.z += b.z; v.w += b.w;
            if (mode == 1) {
                v.x = fmaxf(v.x, 0.f); v.y = fmaxf(v.y, 0.f);
                v.z = fmaxf(v.z, 0.f); v.w = fmaxf(v.w, 0.f);
            }
        }
        split_store(p, AH_OFF + r * 272 + q * 8, AL_OFF + r * 272 + q * 8, v);
    }
    __syncthreads();

    int wm = wid >> 1, wn = wid & 1;
    int grp = lane >> 3, lr = lane & 7;
    unsigned aA = base + AH_OFF + ((wm * 16 + (grp & 1) * 8 + lr) * 136 + (grp >> 1) * 8) * 2;
    unsigned bB = base + WH_OFF + ((wn * 64 + (grp >> 1) * 8 + lr) * 136 + (grp & 1) * 8) * 2;

    float acc[8][4];
#pragma unroll
    for (int b = 0; b < 8; b++)
#pragma unroll
        for (int c = 0; c < 4; c++) acc[b][c] = 0.f;

#pragma unroll 2
    for (int ks = 0; ks < 8; ks++) {
        unsigned ah[4], al[4];
        ldsm4(ah, aA + ks * 32);
        ldsm4(al, aA + 17408 + ks * 32);
#pragma unroll
        for (int nb2 = 0; nb2 < 4; nb2++) {
            unsigned bh[4], bl[4];
            ldsm4(bh, bB + nb2 * 4352 + ks * 32);
            ldsm4(bl, bB + 34816 + nb2 * 4352 + ks * 32);
            mma16816(acc[2 * nb2],     ah, bh[0], bh[1]);
            mma16816(acc[2 * nb2 + 1], ah, bh[2], bh[3]);
            mma16816(acc[2 * nb2],     ah, bl[0], bl[1]);
            mma16816(acc[2 * nb2 + 1], ah, bl[2], bl[3]);
            mma16816(acc[2 * nb2],     al, bh[0], bh[1]);
            mma16816(acc[2 * nb2 + 1], al, bh[2], bh[3]);
        }
    }
    __syncthreads();

    // stage accumulators to smem [64][132] f32 (overwrites A region), coalesced writeout
    float* stg = (float*)p;
#pragma unroll
    for (int nb = 0; nb < 8; nb++)
#pragma unroll
        for (int i = 0; i < 4; i++) {
            int row = wm * 16 + (lane >> 2) + (i >> 1) * 8;
            int col = wn * 64 + nb * 8 + (lane & 3) * 2 + (i & 1);
            stg[row * 132 + col] = acc[nb][i];
        }
    __syncthreads();
#pragma unroll
    for (int i = 0; i < 8; i++) {
        int fi = tid + i * 256;
        int r = fi >> 5, q = fi & 31;
        int rr = r0 + r;
        if (rr < n) {
            float4 v;
            v.x = stg[r * 132 + q * 4 + 0]; v.y = stg[r * 132 + q * 4 + 1];
            v.z = stg[r * 132 + q * 4 + 2]; v.w = stg[r * 132 + q * 4 + 3];
            *(float4*)(Y + (size_t)rr * yLd + blockIdx.y * 128 + q * 4) = v;
            if (Yself) {
                float dv = g_dinv[rr]; float s2 = dv * dv;
                v.x *= s2; v.y *= s2; v.z *= s2; v.w *= s2;
                *(float4*)(Yself + (size_t)rr * HID + q * 4) = v;
            }
        }
    }
}

// ---------------- scatter: warp per edge, vector red ----------------
__global__ void k_scatter(const float* __restrict__ hw, const int* __restrict__ row,
                          const int* __restrict__ col, float* __restrict__ agg, int E) {
    int t = blockIdx.x * blockDim.x + threadIdx.x;
    int e = t >> 5, q = t & 31;
    if (e >= E) return;
    int r = row[e], c = col[e];
    float norm = g_dinv[r] * g_dinv[c];
    float4 v = *(const float4*)(hw + (size_t)r * HID + q * 4);
    v.x *= norm; v.y *= norm; v.z *= norm; v.w *= norm;
    float* p = agg + (size_t)c * HID + q * 4;
    asm volatile("red.global.add.v4.f32 [%0], {%1, %2, %3, %4};"
                 :: "l"(p), "f"(v.x), "f"(v.y), "f"(v.z), "f"(v.w) : "memory");
}

// ---------------- edge kernel: gather+relu (factorized L1) -> HMMA L2 -> L3+sigmoid ----
// 128 edges/block. e1 = relu(P_top[r]+P_bot[c]+be) [128]; h2 = relu(e1@Wc1+bc1) [64];
// out = sigmoid(sum_c h2[c]*(Wc2[c,1]-Wc2[c,0]) + (bc2[1]-bc2[0]))
// 8 warps: wm=wid>>1 (32 edges), wn=wid&1 (n32).
__global__ __launch_bounds__(256)
void k_edge_hmma(const float* __restrict__ P,
                 const int* __restrict__ row, const int* __restrict__ col,
                 const float* __restrict__ be, const float* __restrict__ bc1,
                 const float* __restrict__ Wc2, const float* __restrict__ bc2,
                 float* __restrict__ out, int E) {
    extern __shared__ char p[];
    unsigned base = smem_u32(p);
    int*   sr   = (int*)(p + ESR_OFF);
    int*   sc   = (int*)(p + ESC_OFF);
    float* wdf  = (float*)(p + EWD_OFF);
    float* sbc1 = (float*)(p + EBC_OFF);
    float* eacc = (float*)(p + EAC_OFF);
    int tid = threadIdx.x, wid = tid >> 5, lane = tid & 31;
    int e0 = blockIdx.x * 128;

    if (tid < 128) {
        int e = e0 + tid; if (e >= E) e = E - 1;
        sr[tid] = row[e]; sc[tid] = col[e];
        eacc[tid] = 0.f;
    }
    if (tid < 64) {
        wdf[tid]  = Wc2[tid * 2 + 1] - Wc2[tid * 2];
        sbc1[tid] = bc1[tid];
    }
    {   // stage Wc1t [64][136] h/l  (row = 128 bf16 = 16 x 16B chunks)
        const float4* sH = (const float4*)g_wc1t_h;
        const float4* sL = (const float4*)g_wc1t_l;
#pragma unroll
        for (int i = 0; i < 4; i++) {
            int idx = tid + i * 256;                 // 0..1023
            int r = idx >> 4, seg = idx & 15;
            *(float4*)(p + EWH_OFF + r * 272 + seg * 16) = sH[idx];
            *(float4*)(p + EWL_OFF + r * 272 + seg * 16) = sL[idx];
        }
    }
    __syncthreads();   // sr/sc + eacc ready

    const float4* P4 = (const float4*)P;
#pragma unroll
    for (int i = 0; i < 16; i++) {
        int fi = tid + i * 256;
        int e = fi >> 5, q = fi & 31;
        float4 v = P4[(size_t)sr[e] * 64 + q];
        float4 u = P4[(size_t)sc[e] * 64 + 32 + q];
        float4 b = *(const float4*)(be + q * 4);
        v.x = fmaxf(v.x + u.x + b.x, 0.f);
        v.y = fmaxf(v.y + u.y + b.y, 0.f);
        v.z = fmaxf(v.z + u.z + b.z, 0.f);
        v.w = fmaxf(v.w + u.w + b.w, 0.f);
        split_store(p, EAH_OFF + e * 272 + q * 8, EAL_OFF + e * 272 + q * 8, v);
    }
    __syncthreads();

    int wm = wid >> 1, wn = wid & 1;
    int grp = lane >> 3, lr = lane & 7;
    unsigned aA = base + EAH_OFF + ((wm * 32 + (grp & 1) * 8 + lr) * 136 + (grp >> 1) * 8) * 2;
    unsigned bB = base + EWH_OFF + ((wn * 32 + (grp >> 1) * 8 + lr) * 136 + (grp & 1) * 8) * 2;

    float acc[2][4][4];
#pragma unroll
    for (int a = 0; a < 2; a++)
#pragma unroll
        for (int b = 0; b < 4; b++)
#pragma unroll
            for (int c = 0; c < 4; c++) acc[a][b][c] = 0.f;

#pragma unroll 2
    for (int ks = 0; ks < 8; ks++) {
        unsigned ah0[4], ah1[4], al0[4], al1[4];
        ldsm4(ah0, aA + ks * 32);
        ldsm4(ah1, aA + 4352 + ks * 32);
        ldsm4(al0, aA + 34816 + ks * 32);
        ldsm4(al1, aA + 34816 + 4352 + ks * 32);
#pragma unroll
        for (int nb2 = 0; nb2 < 2; nb2++) {
            unsigned bh[4], bl[4];
            ldsm4(bh, bB + nb2 * 4352 + ks * 32);
            ldsm4(bl, bB + 17408 + nb2 * 4352 + ks * 32);
            mma16816(acc[0][2 * nb2],     ah0, bh[0], bh[1]);
            mma16816(acc[0][2 * nb2 + 1], ah0, bh[2], bh[3]);
            mma16816(acc[1][2 * nb2],     ah1, bh[0], bh[1]);
            mma16816(acc[1][2 * nb2 + 1], ah1, bh[2], bh[3]);
            mma16816(acc[0][2 * nb2],     ah0, bl[0], bl[1]);
            mma16816(acc[0][2 * nb2 + 1], ah0, bl[2], bl[3]);
            mma16816(acc[1][2 * nb2],     ah1, bl[0], bl[1]);
            mma16816(acc[1][2 * nb2 + 1], ah1, bl[2], bl[3]);
            mma16816(acc[0][2 * nb2],     al0, bh[0], bh[1]);
            mma16816(acc[0][2 * nb2 + 1], al0, bh[2], bh[3]);
            mma16816(acc[1][2 * nb2],     al1, bh[0], bh[1]);
            mma16816(acc[1][2 * nb2 + 1], al1, bh[2], bh[3]);
        }
    }

    // epilogue: h2 = relu(acc + bc1); partial dot with wdf; reduce lanes + warps
#pragma unroll
    for (int mf = 0; mf < 2; mf++) {
        float pr = 0.f, pr8 = 0.f;
#pragma unroll
        for (int nb = 0; nb < 4; nb++) {
            int c = wn * 32 + nb * 8 + (lane & 3) * 2;
            pr  += fmaxf(acc[mf][nb][0] + sbc1[c],     0.f) * wdf[c]
                 + fmaxf(acc[mf][nb][1] + sbc1[c + 1], 0.f) * wdf[c + 1];
            pr8 += fmaxf(acc[mf][nb][2] + sbc1[c],     0.f) * wdf[c]
                 + fmaxf(acc[mf][nb][3] + sbc1[c + 1], 0.f) * wdf[c + 1];
        }
#pragma unroll
        for (int o = 1; o <= 2; o <<= 1) {
            pr  += __shfl_xor_sync(0xFFFFFFFFu, pr, o);
            pr8 += __shfl_xor_sync(0xFFFFFFFFu, pr8, o);
        }
        if ((lane & 3) == 0) {
            int rl = wm * 32 + mf * 16 + (lane >> 2);
            atomicAdd(&eacc[rl], pr);
            atomicAdd(&eacc[rl + 8], pr8);
        }
    }
    __syncthreads();
    if (tid < 128) {
        int e = e0 + tid;
        float bd = bc2[1] - bc2[0];
        if (e < E) out[e] = 1.f / (1.f + expf(-(eacc[tid] + bd)));
    }
}

extern "C" void kernel_launch(void* const* d_in, const int* in_sizes, int n_in,
                              void* d_out, int out_size) {
    const float* x   = (const float*)d_in[0];
    const int*   ei  = (const int*)d_in[1];
    const float* W1  = (const float*)d_in[2];
    const float* b1  = (const float*)d_in[3];
    const float* W2  = (const float*)d_in[4];
    const float* b2  = (const float*)d_in[5];
    const float* We  = (const float*)d_in[6];
    const float* be  = (const float*)d_in[7];
    const float* Wc1 = (const float*)d_in[8];
    const float* bc1 = (const float*)d_in[9];
    const float* Wc2 = (const float*)d_in[10];
    const float* bc2 = (const float*)d_in[11];
    float* out = (float*)d_out;

    int n = in_sizes[0] / HID;          // 100000
    int E = in_sizes[1] / 2;            // 500000
    const int* row = ei;
    const int* col = ei + E;

    float *buf0, *buf1, *buf2, *bufP;
    cudaGetSymbolAddress((void**)&buf0, g_buf0);
    cudaGetSymbolAddress((void**)&buf1, g_buf1);
    cudaGetSymbolAddress((void**)&buf2, g_buf2);
    cudaGetSymbolAddress((void**)&bufP, g_bufP);
    __nv_bfloat16 *w1h, *w1l, *w2h, *w2l, *weh, *wel;
    cudaGetSymbolAddress((void**)&w1h, g_w1t_h); cudaGetSymbolAddress((void**)&w1l, g_w1t_l);
    cudaGetSymbolAddress((void**)&w2h, g_w2t_h); cudaGetSymbolAddress((void**)&w2l, g_w2t_l);
    cudaGetSymbolAddress((void**)&weh, g_wet_h); cudaGetSymbolAddress((void**)&wel, g_wet_l);

    static int inited = 0;
    if (!inited) {
        cudaFuncSetAttribute(k_gemm_hmma, cudaFuncAttributeMaxDynamicSharedMemorySize, GEMM_SMEM);
        cudaFuncSetAttribute(k_edge_hmma, cudaFuncAttributeMaxDynamicSharedMemorySize, EDGE_SMEM);
        inited = 1;
    }

    dim3 b256(256);
    int gNode = (n + 255) / 256;
    int gEdge = (E + 255) / 256;
    int gScat = (E * 32 + 255) / 256;
    int gG    = (n + 63) / 64;
    int gM    = (E + 127) / 128;

    // degrees / dinv (deg zero-state invariant; k_dinv resets) + weight prep
    k_deg_count<<<gEdge, b256>>>(col, E);
    k_dinv<<<gNode, b256>>>(n);
    k_prep<<<288, b256>>>(W1, W2, We, Wc1);

    // conv1: hw1 = x@W1 (buf0), agg seeded with self-loop (buf1)
    k_gemm_hmma<<<dim3(gG, 1), b256, GEMM_SMEM>>>(x, nullptr, 0, w1h, w1l, buf0, HID, buf1, n);
    k_scatter<<<gScat, b256>>>(buf0, row, col, buf1, E);

    // conv2: A = relu(agg1+b1); hw2 (buf2), agg2 seeded (buf0)
    k_gemm_hmma<<<dim3(gG, 1), b256, GEMM_SMEM>>>(buf1, b1, 1, w2h, w2l, buf2, HID, buf0, n);
    k_scatter<<<gScat, b256>>>(buf2, row, col, buf0, E);

    // P[N,256] = (agg2+b2) @ [We_top | We_bot]  (grid.y selects half)
    k_gemm_hmma<<<dim3(gG, 2), b256, GEMM_SMEM>>>(buf0, b2, 2, weh, wel, bufP, 256, nullptr, n);

    // edge: gather-add-relu + HMMA layer2 + layer3 + sigmoid
    k_edge_hmma<<<gM, b256, EDGE_SMEM>>>(bufP, row, col, be, bc1, Wc2, bc2, out, E);
}

// round 15
// speedup vs baseline: 8.7312x; 1.1523x over previous
#include <cuda_runtime.h>
#include <cuda_bf16.h>
#include <math.h>

#define NN 100000
#define EE 500000
#define HID 128

// ---------------- scratch (allocation-free rule: __device__ globals) ----------------
__device__ float g_buf0[NN * HID];
__device__ float g_buf1[NN * HID];
__device__ float g_buf2[NN * HID];
__device__ float g_bufP[NN * 256];
__device__ float g_dinv[NN];
__device__ int   g_deg[NN];          // invariant: zero at kernel_launch entry (reset by k_scan3)
__device__ int   g_off[NN + 1];
__device__ int   g_cursor[NN];
__device__ int   g_csr[EE];
__device__ int   g_bsum[512];
__device__ int   g_boff[512];

// bf16 hi/lo transposed weight images, plain row-major Wt[n][k]
__device__ __nv_bfloat16 g_w1t_h[16384],  g_w1t_l[16384];
__device__ __nv_bfloat16 g_w2t_h[16384],  g_w2t_l[16384];
__device__ __nv_bfloat16 g_wet_h[32768],  g_wet_l[32768];    // two 128x128 halves of We
__device__ __nv_bfloat16 g_wc1t_h[8192],  g_wc1t_l[8192];    // Wt[64][128]

// GEMM smem layout: 64-row A tile (2 CTAs/SM). Rows padded to 136 bf16 = 272B.
#define AH_OFF 0
#define AL_OFF 17408
#define WH_OFF 34816
#define WL_OFF 69632
#define GEMM_SMEM 104448

// Edge kernel smem layout (128-edge A tile)
#define EAH_OFF 0
#define EAL_OFF 34816
#define EWH_OFF 69632
#define EWL_OFF 87040
#define ESR_OFF 104448
#define ESC_OFF 104960
#define EWD_OFF 105472
#define EBC_OFF 105728
#define EAC_OFF 105984
#define EDGE_SMEM 106496

// ---------------- PTX helpers (base ISA: ldmatrix + mma.sync, sm_80+) ----------------
__device__ __forceinline__ unsigned smem_u32(const void* p) {
    unsigned a;
    asm("{ .reg .u64 t; cvta.to.shared.u64 t, %1; cvt.u32.u64 %0, t; }" : "=r"(a) : "l"(p));
    return a;
}
__device__ __forceinline__ void ldsm4(unsigned* r, unsigned addr) {
    asm volatile("ldmatrix.sync.aligned.m8n8.x4.shared.b16 {%0,%1,%2,%3}, [%4];"
                 : "=r"(r[0]), "=r"(r[1]), "=r"(r[2]), "=r"(r[3]) : "r"(addr));
}
__device__ __forceinline__ void mma16816(float* d, const unsigned* a, unsigned b0, unsigned b1) {
    asm volatile("mma.sync.aligned.m16n8k16.row.col.f32.bf16.bf16.f32 "
                 "{%0,%1,%2,%3}, {%4,%5,%6,%7}, {%8,%9}, {%0,%1,%2,%3};"
                 : "+f"(d[0]), "+f"(d[1]), "+f"(d[2]), "+f"(d[3])
                 : "r"(a[0]), "r"(a[1]), "r"(a[2]), "r"(a[3]), "r"(b0), "r"(b1));
}
__device__ __forceinline__ void split_store(char* p, unsigned offH, unsigned offL, float4 v) {
    __nv_bfloat16 h0 = __float2bfloat16(v.x), h1 = __float2bfloat16(v.y);
    __nv_bfloat16 h2 = __float2bfloat16(v.z), h3 = __float2bfloat16(v.w);
    __nv_bfloat16 l0 = __float2bfloat16(v.x - __bfloat162float(h0));
    __nv_bfloat16 l1 = __float2bfloat16(v.y - __bfloat162float(h1));
    __nv_bfloat16 l2 = __float2bfloat16(v.z - __bfloat162float(h2));
    __nv_bfloat16 l3 = __float2bfloat16(v.w - __bfloat162float(h3));
    unsigned hp0 = ((unsigned)__bfloat16_as_ushort(h1) << 16) | __bfloat16_as_ushort(h0);
    unsigned hp1 = ((unsigned)__bfloat16_as_ushort(h3) << 16) | __bfloat16_as_ushort(h2);
    unsigned lp0 = ((unsigned)__bfloat16_as_ushort(l1) << 16) | __bfloat16_as_ushort(l0);
    unsigned lp1 = ((unsigned)__bfloat16_as_ushort(l3) << 16) | __bfloat16_as_ushort(l2);
    *(uint2*)(p + offH) = make_uint2(hp0, hp1);
    *(uint2*)(p + offL) = make_uint2(lp0, lp1);
}

// ---------------- degree / CSR build ----------------
__global__ void k_deg_count(const int* __restrict__ col, int E) {
    int i = blockIdx.x * blockDim.x + threadIdx.x;
    if (i < E) atomicAdd(&g_deg[col[i]], 1);
}
// block-level reduce of deg into g_bsum
__global__ void k_scan1(int n) {
    __shared__ int s[256];
    int i = blockIdx.x * 256 + threadIdx.x;
    s[threadIdx.x] = (i < n) ? g_deg[i] : 0;
    __syncthreads();
#pragma unroll
    for (int d = 128; d > 0; d >>= 1) {
        if (threadIdx.x < d) s[threadIdx.x] += s[threadIdx.x + d];
        __syncthreads();
    }
    if (threadIdx.x == 0) g_bsum[blockIdx.x] = s[0];
}
// exclusive scan of block sums (nb <= 512)
__global__ void k_scan2(int nb) {
    __shared__ int s[512];
    int t = threadIdx.x;
    s[t] = (t < nb) ? g_bsum[t] : 0;
    __syncthreads();
#pragma unroll
    for (int d = 1; d < 512; d <<= 1) {
        int v = (t >= d) ? s[t - d] : 0;
        __syncthreads();
        s[t] += v;
        __syncthreads();
    }
    if (t < nb) g_boff[t] = (t == 0) ? 0 : s[t - 1];
}
// per-element exclusive offsets + cursor + dinv; reset deg (zero-state invariant)
__global__ void k_scan3(int n, int E) {
    __shared__ int s[256];
    int i = blockIdx.x * 256 + threadIdx.x;
    int v = (i < n) ? g_deg[i] : 0;
    s[threadIdx.x] = v;
    __syncthreads();
#pragma unroll
    for (int d = 1; d < 256; d <<= 1) {
        int t = (threadIdx.x >= d) ? s[threadIdx.x - d] : 0;
        __syncthreads();
        s[threadIdx.x] += t;
        __syncthreads();
    }
    if (i < n) {
        int off = g_boff[blockIdx.x] + s[threadIdx.x] - v;   // exclusive
        g_off[i] = off;
        g_cursor[i] = off;
        g_dinv[i] = rsqrtf((float)(v + 1));
        g_deg[i] = 0;
    }
    if (blockIdx.x == 0 && threadIdx.x == 0) g_off[n] = E;
}
__global__ void k_fill(const int* __restrict__ row, const int* __restrict__ col, int E) {
    int i = blockIdx.x * blockDim.x + threadIdx.x;
    if (i < E) {
        int pos = atomicAdd(&g_cursor[col[i]], 1);
        g_csr[pos] = row[i];
    }
}

// ---------------- weight prep: transpose + bf16 hi/lo split, plain [n][k] ----------------
__global__ void k_prep(const float* __restrict__ W1, const float* __restrict__ W2,
                       const float* __restrict__ We, const float* __restrict__ Wc1) {
    int idx = blockIdx.x * blockDim.x + threadIdx.x;
    const float* src; __nv_bfloat16 *dh, *dl; int n, k, off;
    if (idx < 16384)      { int t = idx;         n = t >> 7; k = t & 127; src = &W1[k * 128 + n];         dh = g_w1t_h;         dl = g_w1t_l;         off = n * 128 + k; }
    else if (idx < 32768) { int t = idx - 16384; n = t >> 7; k = t & 127; src = &W2[k * 128 + n];         dh = g_w2t_h;         dl = g_w2t_l;         off = n * 128 + k; }
    else if (idx < 49152) { int t = idx - 32768; n = t >> 7; k = t & 127; src = &We[k * 128 + n];         dh = g_wet_h;         dl = g_wet_l;         off = n * 128 + k; }
    else if (idx < 65536) { int t = idx - 49152; n = t >> 7; k = t & 127; src = &We[(128 + k) * 128 + n]; dh = g_wet_h + 16384; dl = g_wet_l + 16384; off = n * 128 + k; }
    else if (idx < 73728) { int t = idx - 65536; n = t >> 7; k = t & 127; src = &Wc1[k * 64 + n];         dh = g_wc1t_h;        dl = g_wc1t_l;        off = n * 128 + k; }
    else return;
    float v = *src;
    __nv_bfloat16 hi = __float2bfloat16(v);
    __nv_bfloat16 lo = __float2bfloat16(v - __bfloat162float(hi));
    dh[off] = hi; dl[off] = lo;
}

// ---------------- HMMA GEMM: Y[r, gy*128+c] = transform(X)[r,:] @ Wt^T (hi/lo split) ----
// mode: 0 = X, 1 = relu(X+bias), 2 = X+bias.  doScale: multiply result by dinv[r] (Z form).
// Block 64 rows x 128 cols, K=128 resident; smem 104.4KB -> 2 CTAs/SM.
__global__ __launch_bounds__(256)
void k_gemm_hmma(const float* __restrict__ X, const float* __restrict__ bias, int mode,
                 const __nv_bfloat16* __restrict__ WtH, const __nv_bfloat16* __restrict__ WtL,
                 float* __restrict__ Y, int yLd, int doScale, int n) {
    extern __shared__ char p[];
    unsigned base = smem_u32(p);
    int tid = threadIdx.x, wid = tid >> 5, lane = tid & 31;
    int r0 = blockIdx.x * 64;

    // stage weights [128][136] h/l  (row = 128 bf16 = 16 x 16B chunks)
    {
        const float4* sH = (const float4*)(WtH + blockIdx.y * 16384);
        const float4* sL = (const float4*)(WtL + blockIdx.y * 16384);
#pragma unroll
        for (int i = 0; i < 8; i++) {
            int idx = tid + i * 256;                 // 0..2047
            int row = idx >> 4, seg = idx & 15;
            *(float4*)(p + WH_OFF + row * 272 + seg * 16) = sH[idx];
            *(float4*)(p + WL_OFF + row * 272 + seg * 16) = sL[idx];
        }
    }
    // stage A: transform + hi/lo split into [64][136] bf16
#pragma unroll
    for (int i = 0; i < 8; i++) {
        int fi = tid + i * 256;                      // 0..2047
        int r = fi >> 5, q = fi & 31;
        int rr = r0 + r; if (rr >= n) rr = n - 1;
        float4 v = *(const float4*)(X + (size_t)rr * HID + q * 4);
        if (mode) {
            float4 b = *(const float4*)(bias + q * 4);
            v.x += b.x; v.y += b.y; v.z += b.z; v.w += b.w;
            if (mode == 1) {
                v.x = fmaxf(v.x, 0.f); v.y = fmaxf(v.y, 0.f);
                v.z = fmaxf(v.z, 0.f); v.w = fmaxf(v.w, 0.f);
            }
        }
        split_store(p, AH_OFF + r * 272 + q * 8, AL_OFF + r * 272 + q * 8, v);
    }
    __syncthreads();

    int wm = wid >> 1, wn = wid & 1;
    int grp = lane >> 3, lr = lane & 7;
    unsigned aA = base + AH_OFF + ((wm * 16 + (grp & 1) * 8 + lr) * 136 + (grp >> 1) * 8) * 2;
    unsigned bB = base + WH_OFF + ((wn * 64 + (grp >> 1) * 8 + lr) * 136 + (grp & 1) * 8) * 2;

    float acc[8][4];
#pragma unroll
    for (int b = 0; b < 8; b++)
#pragma unroll
        for (int c = 0; c < 4; c++) acc[b][c] = 0.f;

#pragma unroll 2
    for (int ks = 0; ks < 8; ks++) {
        unsigned ah[4], al[4];
        ldsm4(ah, aA + ks * 32);
        ldsm4(al, aA + 17408 + ks * 32);
#pragma unroll
        for (int nb2 = 0; nb2 < 4; nb2++) {
            unsigned bh[4], bl[4];
            ldsm4(bh, bB + nb2 * 4352 + ks * 32);
            ldsm4(bl, bB + 34816 + nb2 * 4352 + ks * 32);
            mma16816(acc[2 * nb2],     ah, bh[0], bh[1]);
            mma16816(acc[2 * nb2 + 1], ah, bh[2], bh[3]);
            mma16816(acc[2 * nb2],     ah, bl[0], bl[1]);
            mma16816(acc[2 * nb2 + 1], ah, bl[2], bl[3]);
            mma16816(acc[2 * nb2],     al, bh[0], bh[1]);
            mma16816(acc[2 * nb2 + 1], al, bh[2], bh[3]);
        }
    }
    __syncthreads();

    // stage accumulators to smem [64][132] f32 (overwrites A region), coalesced writeout
    float* stg = (float*)p;
#pragma unroll
    for (int nb = 0; nb < 8; nb++)
#pragma unroll
        for (int i = 0; i < 4; i++) {
            int row = wm * 16 + (lane >> 2) + (i >> 1) * 8;
            int col = wn * 64 + nb * 8 + (lane & 3) * 2 + (i & 1);
            stg[row * 132 + col] = acc[nb][i];
        }
    __syncthreads();
#pragma unroll
    for (int i = 0; i < 8; i++) {
        int fi = tid + i * 256;
        int r = fi >> 5, q = fi & 31;
        int rr = r0 + r;
        if (rr < n) {
            float4 v;
            v.x = stg[r * 132 + q * 4 + 0]; v.y = stg[r * 132 + q * 4 + 1];
            v.z = stg[r * 132 + q * 4 + 2]; v.w = stg[r * 132 + q * 4 + 3];
            if (doScale) {
                float dv = g_dinv[rr];
                v.x *= dv; v.y *= dv; v.z *= dv; v.w *= dv;
            }
            *(float4*)(Y + (size_t)rr * yLd + blockIdx.y * 128 + q * 4) = v;
        }
    }
}

// ---------------- aggregate: warp per node, CSR gather ----------------
// agg[c] = dinv[c] * (Z[c] + sum_{r in in(c)} Z[r])   with Z = dinv * hw
__global__ __launch_bounds__(256)
void k_aggregate(const float* __restrict__ Z, float* __restrict__ agg, int n) {
    int gw = (blockIdx.x * 256 + threadIdx.x) >> 5;
    int q = threadIdx.x & 31;
    if (gw >= n) return;
    int s = g_off[gw], e = g_off[gw + 1];
    const float4* Z4 = (const float4*)Z;
    float4 acc = Z4[(size_t)gw * 32 + q];
    for (int i = s; i < e; i++) {
        int r = g_csr[i];
        float4 z = Z4[(size_t)r * 32 + q];
        acc.x += z.x; acc.y += z.y; acc.z += z.z; acc.w += z.w;
    }
    float dv = g_dinv[gw];
    acc.x *= dv; acc.y *= dv; acc.z *= dv; acc.w *= dv;
    ((float4*)agg)[(size_t)gw * 32 + q] = acc;
}

// ---------------- edge kernel: gather+relu (factorized L1) -> HMMA L2 -> L3+sigmoid ----
// 128 edges/block. e1 = relu(P_top[r]+P_bot[c]+be) [128]; h2 = relu(e1@Wc1+bc1) [64];
// out = sigmoid(sum_c h2[c]*(Wc2[c,1]-Wc2[c,0]) + (bc2[1]-bc2[0]))
__global__ __launch_bounds__(256)
void k_edge_hmma(const float* __restrict__ P,
                 const int* __restrict__ row, const int* __restrict__ col,
                 const float* __restrict__ be, const float* __restrict__ bc1,
                 const float* __restrict__ Wc2, const float* __restrict__ bc2,
                 float* __restrict__ out, int E) {
    extern __shared__ char p[];
    unsigned base = smem_u32(p);
    int*   sr   = (int*)(p + ESR_OFF);
    int*   sc   = (int*)(p + ESC_OFF);
    float* wdf  = (float*)(p + EWD_OFF);
    float* sbc1 = (float*)(p + EBC_OFF);
    float* eacc = (float*)(p + EAC_OFF);
    int tid = threadIdx.x, wid = tid >> 5, lane = tid & 31;
    int e0 = blockIdx.x * 128;

    if (tid < 128) {
        int e = e0 + tid; if (e >= E) e = E - 1;
        sr[tid] = row[e]; sc[tid] = col[e];
        eacc[tid] = 0.f;
    }
    if (tid < 64) {
        wdf[tid]  = Wc2[tid * 2 + 1] - Wc2[tid * 2];
        sbc1[tid] = bc1[tid];
    }
    {   // stage Wc1t [64][136] h/l  (row = 128 bf16 = 16 x 16B chunks)
        const float4* sH = (const float4*)g_wc1t_h;
        const float4* sL = (const float4*)g_wc1t_l;
#pragma unroll
        for (int i = 0; i < 4; i++) {
            int idx = tid + i * 256;                 // 0..1023
            int r = idx >> 4, seg = idx & 15;
            *(float4*)(p + EWH_OFF + r * 272 + seg * 16) = sH[idx];
            *(float4*)(p + EWL_OFF + r * 272 + seg * 16) = sL[idx];
        }
    }
    __syncthreads();   // sr/sc + eacc ready

    const float4* P4 = (const float4*)P;
#pragma unroll
    for (int i = 0; i < 16; i++) {
        int fi = tid + i * 256;
        int e = fi >> 5, q = fi & 31;
        float4 v = P4[(size_t)sr[e] * 64 + q];
        float4 u = P4[(size_t)sc[e] * 64 + 32 + q];
        float4 b = *(const float4*)(be + q * 4);
        v.x = fmaxf(v.x + u.x + b.x, 0.f);
        v.y = fmaxf(v.y + u.y + b.y, 0.f);
        v.z = fmaxf(v.z + u.z + b.z, 0.f);
        v.w = fmaxf(v.w + u.w + b.w, 0.f);
        split_store(p, EAH_OFF + e * 272 + q * 8, EAL_OFF + e * 272 + q * 8, v);
    }
    __syncthreads();

    int wm = wid >> 1, wn = wid & 1;
    int grp = lane >> 3, lr = lane & 7;
    unsigned aA = base + EAH_OFF + ((wm * 32 + (grp & 1) * 8 + lr) * 136 + (grp >> 1) * 8) * 2;
    unsigned bB = base + EWH_OFF + ((wn * 32 + (grp >> 1) * 8 + lr) * 136 + (grp & 1) * 8) * 2;

    float acc[2][4][4];
#pragma unroll
    for (int a = 0; a < 2; a++)
#pragma unroll
        for (int b = 0; b < 4; b++)
#pragma unroll
            for (int c = 0; c < 4; c++) acc[a][b][c] = 0.f;

#pragma unroll 2
    for (int ks = 0; ks < 8; ks++) {
        unsigned ah0[4], ah1[4], al0[4], al1[4];
        ldsm4(ah0, aA + ks * 32);
        ldsm4(ah1, aA + 4352 + ks * 32);
        ldsm4(al0, aA + 34816 + ks * 32);
        ldsm4(al1, aA + 34816 + 4352 + ks * 32);
#pragma unroll
        for (int nb2 = 0; nb2 < 2; nb2++) {
            unsigned bh[4], bl[4];
            ldsm4(bh, bB + nb2 * 4352 + ks * 32);
            ldsm4(bl, bB + 17408 + nb2 * 4352 + ks * 32);
            mma16816(acc[0][2 * nb2],     ah0, bh[0], bh[1]);
            mma16816(acc[0][2 * nb2 + 1], ah0, bh[2], bh[3]);
            mma16816(acc[1][2 * nb2],     ah1, bh[0], bh[1]);
            mma16816(acc[1][2 * nb2 + 1], ah1, bh[2], bh[3]);
            mma16816(acc[0][2 * nb2],     ah0, bl[0], bl[1]);
            mma16816(acc[0][2 * nb2 + 1], ah0, bl[2], bl[3]);
            mma16816(acc[1][2 * nb2],     ah1, bl[0], bl[1]);
            mma16816(acc[1][2 * nb2 + 1], ah1, bl[2], bl[3]);
            mma16816(acc[0][2 * nb2],     al0, bh[0], bh[1]);
            mma16816(acc[0][2 * nb2 + 1], al0, bh[2], bh[3]);
            mma16816(acc[1][2 * nb2],     al1, bh[0], bh[1]);
            mma16816(acc[1][2 * nb2 + 1], al1, bh[2], bh[3]);
        }
    }

    // epilogue: h2 = relu(acc + bc1); partial dot with wdf; reduce lanes + warps
#pragma unroll
    for (int mf = 0; mf < 2; mf++) {
        float pr = 0.f, pr8 = 0.f;
#pragma unroll
        for (int nb = 0; nb < 4; nb++) {
            int c = wn * 32 + nb * 8 + (lane & 3) * 2;
            pr  += fmaxf(acc[mf][nb][0] + sbc1[c],     0.f) * wdf[c]
                 + fmaxf(acc[mf][nb][1] + sbc1[c + 1], 0.f) * wdf[c + 1];
            pr8 += fmaxf(acc[mf][nb][2] + sbc1[c],     0.f) * wdf[c]
                 + fmaxf(acc[mf][nb][3] + sbc1[c + 1], 0.f) * wdf[c + 1];
        }
#pragma unroll
        for (int o = 1; o <= 2; o <<= 1) {
            pr  += __shfl_xor_sync(0xFFFFFFFFu, pr, o);
            pr8 += __shfl_xor_sync(0xFFFFFFFFu, pr8, o);
        }
        if ((lane & 3) == 0) {
            int rl = wm * 32 + mf * 16 + (lane >> 2);
            atomicAdd(&eacc[rl], pr);
            atomicAdd(&eacc[rl + 8], pr8);
        }
    }
    __syncthreads();
    if (tid < 128) {
        int e = e0 + tid;
        float bd = bc2[1] - bc2[0];
        if (e < E) out[e] = 1.f / (1.f + expf(-(eacc[tid] + bd)));
    }
}

extern "C" void kernel_launch(void* const* d_in, const int* in_sizes, int n_in,
                              void* d_out, int out_size) {
    const float* x   = (const float*)d_in[0];
    const int*   ei  = (const int*)d_in[1];
    const float* W1  = (const float*)d_in[2];
    const float* b1  = (const float*)d_in[3];
    const float* W2  = (const float*)d_in[4];
    const float* b2  = (const float*)d_in[5];
    const float* We  = (const float*)d_in[6];
    const float* be  = (const float*)d_in[7];
    const float* Wc1 = (const float*)d_in[8];
    const float* bc1 = (const float*)d_in[9];
    const float* Wc2 = (const float*)d_in[10];
    const float* bc2 = (const float*)d_in[11];
    float* out = (float*)d_out;

    int n = in_sizes[0] / HID;          // 100000
    int E = in_sizes[1] / 2;            // 500000
    const int* row = ei;
    const int* col = ei + E;

    float *buf0, *buf1, *buf2, *bufP;
    cudaGetSymbolAddress((void**)&buf0, g_buf0);
    cudaGetSymbolAddress((void**)&buf1, g_buf1);
    cudaGetSymbolAddress((void**)&buf2, g_buf2);
    cudaGetSymbolAddress((void**)&bufP, g_bufP);
    __nv_bfloat16 *w1h, *w1l, *w2h, *w2l, *weh, *wel;
    cudaGetSymbolAddress((void**)&w1h, g_w1t_h); cudaGetSymbolAddress((void**)&w1l, g_w1t_l);
    cudaGetSymbolAddress((void**)&w2h, g_w2t_h); cudaGetSymbolAddress((void**)&w2l, g_w2t_l);
    cudaGetSymbolAddress((void**)&weh, g_wet_h); cudaGetSymbolAddress((void**)&wel, g_wet_l);

    static int inited = 0;
    if (!inited) {
        cudaFuncSetAttribute(k_gemm_hmma, cudaFuncAttributeMaxDynamicSharedMemorySize, GEMM_SMEM);
        cudaFuncSetAttribute(k_edge_hmma, cudaFuncAttributeMaxDynamicSharedMemorySize, EDGE_SMEM);
        inited = 1;
    }

    dim3 b256(256);
    int gEdge = (E + 255) / 256;
    int gScanB = (n + 255) / 256;      // 391
    int gG    = (n + 63) / 64;
    int gAgg  = (n + 7) / 8;           // warp per node, 8 warps/block
    int gM    = (E + 127) / 128;

    // CSR build (deg zero-state invariant; k_scan3 resets) + weight prep
    k_deg_count<<<gEdge, b256>>>(col, E);
    k_scan1<<<gScanB, b256>>>(n);
    k_scan2<<<1, 512>>>(gScanB);
    k_scan3<<<gScanB, b256>>>(n, E);
    k_fill<<<gEdge, b256>>>(row, col, E);
    k_prep<<<288, b256>>>(W1, W2, We, Wc1);

    // conv1: Z1 = dinv * (x@W1) (buf0); agg1 = D^-1/2 (A+I) D^-1/2 xW1 (buf1)
    k_gemm_hmma<<<dim3(gG, 1), b256, GEMM_SMEM>>>(x, nullptr, 0, w1h, w1l, buf0, HID, 1, n);
    k_aggregate<<<gAgg, b256>>>(buf0, buf1, n);

    // conv2: A = relu(agg1+b1); Z2 = dinv * (A@W2) (buf2); agg2 (buf0)
    k_gemm_hmma<<<dim3(gG, 1), b256, GEMM_SMEM>>>(buf1, b1, 1, w2h, w2l, buf2, HID, 1, n);
    k_aggregate<<<gAgg, b256>>>(buf2, buf0, n);

    // P[N,256] = (agg2+b2) @ [We_top | We_bot]  (grid.y selects half)
    k_gemm_hmma<<<dim3(gG, 2), b256, GEMM_SMEM>>>(buf0, b2, 2, weh, wel, bufP, 256, 0, n);

    // edge: gather-add-relu + HMMA layer2 + layer3 + sigmoid
    k_edge_hmma<<<gM, b256, EDGE_SMEM>>>(bufP, row, col, be, bc1, Wc2, bc2, out, E);
}

// round 16
// speedup vs baseline: 9.3243x; 1.0679x over previous
#include <cuda_runtime.h>
#include <cuda_bf16.h>
#include <math.h>

#define NN 100000
#define EE 500000
#define HID 128

// ---------------- scratch (allocation-free rule: __device__ globals) ----------------
__device__ float g_buf0[NN * HID];
__device__ float g_buf1[NN * HID];
__device__ float g_buf2[NN * HID];
__device__ float g_bufP[NN * 256];
__device__ float g_dinv[NN];
__device__ int   g_deg[NN];          // invariant: zero at kernel_launch entry (reset by k_scan3)
__device__ int   g_off[NN + 1];
__device__ int   g_cursor[NN];
__device__ int   g_csr[EE];
__device__ int   g_bsum[512];
__device__ int   g_boff[512];

// bf16 hi/lo transposed weight images, plain row-major Wt[n][k]
__device__ __nv_bfloat16 g_w1t_h[16384],  g_w1t_l[16384];
__device__ __nv_bfloat16 g_w2t_h[16384],  g_w2t_l[16384];
__device__ __nv_bfloat16 g_wet_h[32768],  g_wet_l[32768];    // two 128x128 halves of We
__device__ __nv_bfloat16 g_wc1t_h[8192],  g_wc1t_l[8192];    // Wt[64][128]

// GEMM smem layout: 64-row A tile (2 CTAs/SM). Rows padded to 136 bf16 = 272B.
#define AH_OFF 0
#define AL_OFF 17408
#define WH_OFF 34816
#define WL_OFF 69632
#define GEMM_SMEM 104448

// Edge kernel smem layout (128-edge A tile)
#define EAH_OFF 0
#define EAL_OFF 34816
#define EWH_OFF 69632
#define EWL_OFF 87040
#define ESR_OFF 104448
#define ESC_OFF 104960
#define EWD_OFF 105472
#define EBC_OFF 105728
#define EAC_OFF 105984
#define EDGE_SMEM 106496

// ---------------- PTX helpers (base ISA: ldmatrix + mma.sync, sm_80+) ----------------
__device__ __forceinline__ unsigned smem_u32(const void* p) {
    unsigned a;
    asm("{ .reg .u64 t; cvta.to.shared.u64 t, %1; cvt.u32.u64 %0, t; }" : "=r"(a) : "l"(p));
    return a;
}
__device__ __forceinline__ void ldsm4(unsigned* r, unsigned addr) {
    asm volatile("ldmatrix.sync.aligned.m8n8.x4.shared.b16 {%0,%1,%2,%3}, [%4];"
                 : "=r"(r[0]), "=r"(r[1]), "=r"(r[2]), "=r"(r[3]) : "r"(addr));
}
__device__ __forceinline__ void mma16816(float* d, const unsigned* a, unsigned b0, unsigned b1) {
    asm volatile("mma.sync.aligned.m16n8k16.row.col.f32.bf16.bf16.f32 "
                 "{%0,%1,%2,%3}, {%4,%5,%6,%7}, {%8,%9}, {%0,%1,%2,%3};"
                 : "+f"(d[0]), "+f"(d[1]), "+f"(d[2]), "+f"(d[3])
                 : "r"(a[0]), "r"(a[1]), "r"(a[2]), "r"(a[3]), "r"(b0), "r"(b1));
}
__device__ __forceinline__ void split_store(char* p, unsigned offH, unsigned offL, float4 v) {
    __nv_bfloat16 h0 = __float2bfloat16(v.x), h1 = __float2bfloat16(v.y);
    __nv_bfloat16 h2 = __float2bfloat16(v.z), h3 = __float2bfloat16(v.w);
    __nv_bfloat16 l0 = __float2bfloat16(v.x - __bfloat162float(h0));
    __nv_bfloat16 l1 = __float2bfloat16(v.y - __bfloat162float(h1));
    __nv_bfloat16 l2 = __float2bfloat16(v.z - __bfloat162float(h2));
    __nv_bfloat16 l3 = __float2bfloat16(v.w - __bfloat162float(h3));
    unsigned hp0 = ((unsigned)__bfloat16_as_ushort(h1) << 16) | __bfloat16_as_ushort(h0);
    unsigned hp1 = ((unsigned)__bfloat16_as_ushort(h3) << 16) | __bfloat16_as_ushort(h2);
    unsigned lp0 = ((unsigned)__bfloat16_as_ushort(l1) << 16) | __bfloat16_as_ushort(l0);
    unsigned lp1 = ((unsigned)__bfloat16_as_ushort(l3) << 16) | __bfloat16_as_ushort(l2);
    *(uint2*)(p + offH) = make_uint2(hp0, hp1);
    *(uint2*)(p + offL) = make_uint2(lp0, lp1);
}

// ---------------- degree / CSR build ----------------
__global__ void k_deg_count(const int* __restrict__ col, int E) {
    int i = blockIdx.x * blockDim.x + threadIdx.x;
    if (i < E) atomicAdd(&g_deg[col[i]], 1);
}
__global__ void k_scan1(int n) {
    __shared__ int s[256];
    int i = blockIdx.x * 256 + threadIdx.x;
    s[threadIdx.x] = (i < n) ? g_deg[i] : 0;
    __syncthreads();
#pragma unroll
    for (int d = 128; d > 0; d >>= 1) {
        if (threadIdx.x < d) s[threadIdx.x] += s[threadIdx.x + d];
        __syncthreads();
    }
    if (threadIdx.x == 0) g_bsum[blockIdx.x] = s[0];
}
__global__ void k_scan2(int nb) {
    __shared__ int s[512];
    int t = threadIdx.x;
    s[t] = (t < nb) ? g_bsum[t] : 0;
    __syncthreads();
#pragma unroll
    for (int d = 1; d < 512; d <<= 1) {
        int v = (t >= d) ? s[t - d] : 0;
        __syncthreads();
        s[t] += v;
        __syncthreads();
    }
    if (t < nb) g_boff[t] = (t == 0) ? 0 : s[t - 1];
}
// per-element exclusive offsets + cursor + dinv; reset deg (zero-state invariant)
__global__ void k_scan3(int n, int E) {
    __shared__ int s[256];
    int i = blockIdx.x * 256 + threadIdx.x;
    int v = (i < n) ? g_deg[i] : 0;
    s[threadIdx.x] = v;
    __syncthreads();
#pragma unroll
    for (int d = 1; d < 256; d <<= 1) {
        int t = (threadIdx.x >= d) ? s[threadIdx.x - d] : 0;
        __syncthreads();
        s[threadIdx.x] += t;
        __syncthreads();
    }
    if (i < n) {
        int off = g_boff[blockIdx.x] + s[threadIdx.x] - v;   // exclusive
        g_off[i] = off;
        g_cursor[i] = off;
        g_dinv[i] = rsqrtf((float)(v + 1));
        g_deg[i] = 0;
    }
    if (blockIdx.x == 0 && threadIdx.x == 0) g_off[n] = E;
}
__global__ void k_fill(const int* __restrict__ row, const int* __restrict__ col, int E) {
    int i = blockIdx.x * blockDim.x + threadIdx.x;
    if (i < E) {
        int pos = atomicAdd(&g_cursor[col[i]], 1);
        g_csr[pos] = row[i];
    }
}

// ---------------- weight prep: transpose + bf16 hi/lo split, plain [n][k] ----------------
__global__ void k_prep(const float* __restrict__ W1, const float* __restrict__ W2,
                       const float* __restrict__ We, const float* __restrict__ Wc1) {
    int idx = blockIdx.x * blockDim.x + threadIdx.x;
    const float* src; __nv_bfloat16 *dh, *dl; int n, k, off;
    if (idx < 16384)      { int t = idx;         n = t >> 7; k = t & 127; src = &W1[k * 128 + n];         dh = g_w1t_h;         dl = g_w1t_l;         off = n * 128 + k; }
    else if (idx < 32768) { int t = idx - 16384; n = t >> 7; k = t & 127; src = &W2[k * 128 + n];         dh = g_w2t_h;         dl = g_w2t_l;         off = n * 128 + k; }
    else if (idx < 49152) { int t = idx - 32768; n = t >> 7; k = t & 127; src = &We[k * 128 + n];         dh = g_wet_h;         dl = g_wet_l;         off = n * 128 + k; }
    else if (idx < 65536) { int t = idx - 49152; n = t >> 7; k = t & 127; src = &We[(128 + k) * 128 + n]; dh = g_wet_h + 16384; dl = g_wet_l + 16384; off = n * 128 + k; }
    else if (idx < 73728) { int t = idx - 65536; n = t >> 7; k = t & 127; src = &Wc1[k * 64 + n];         dh = g_wc1t_h;        dl = g_wc1t_l;        off = n * 128 + k; }
    else return;
    float v = *src;
    __nv_bfloat16 hi = __float2bfloat16(v);
    __nv_bfloat16 lo = __float2bfloat16(v - __bfloat162float(hi));
    dh[off] = hi; dl[off] = lo;
}

// ---------------- HMMA GEMM: Y[r, gy*128+c] = transform(X)[r,:] @ Wt^T (hi/lo split) ----
// mode: 0 = X, 1 = relu(X+bias), 2 = X+bias.
// Block 64 rows x 128 cols, K=128 resident; smem 104.4KB -> 2 CTAs/SM.
// 8 warps: wm=wid>>2 owns m32, wn=wid&3 owns n32 (8 LDSM / 24 MMA per warp-ks).
__global__ __launch_bounds__(256)
void k_gemm_hmma(const float* __restrict__ X, const float* __restrict__ bias, int mode,
                 const __nv_bfloat16* __restrict__ WtH, const __nv_bfloat16* __restrict__ WtL,
                 float* __restrict__ Y, int yLd, int n) {
    extern __shared__ char p[];
    unsigned base = smem_u32(p);
    int tid = threadIdx.x, wid = tid >> 5, lane = tid & 31;
    int r0 = blockIdx.x * 64;

    // stage weights [128][136] h/l  (row = 128 bf16 = 16 x 16B chunks)
    {
        const float4* sH = (const float4*)(WtH + blockIdx.y * 16384);
        const float4* sL = (const float4*)(WtL + blockIdx.y * 16384);
#pragma unroll
        for (int i = 0; i < 8; i++) {
            int idx = tid + i * 256;                 // 0..2047
            int row = idx >> 4, seg = idx & 15;
            *(float4*)(p + WH_OFF + row * 272 + seg * 16) = sH[idx];
            *(float4*)(p + WL_OFF + row * 272 + seg * 16) = sL[idx];
        }
    }
    // stage A: transform + hi/lo split into [64][136] bf16
#pragma unroll
    for (int i = 0; i < 8; i++) {
        int fi = tid + i * 256;                      // 0..2047
        int r = fi >> 5, q = fi & 31;
        int rr = r0 + r; if (rr >= n) rr = n - 1;
        float4 v = *(const float4*)(X + (size_t)rr * HID + q * 4);
        if (mode) {
            float4 b = *(const float4*)(bias + q * 4);
            v.x += b.x; v.y += b.y; v.z += b.z; v.w += b.w;
            if (mode == 1) {
                v.x = fmaxf(v.x, 0.f); v.y = fmaxf(v.y, 0.f);
                v.z = fmaxf(v.z, 0.f); v.w = fmaxf(v.w, 0.f);
            }
        }
        split_store(p, AH_OFF + r * 272 + q * 8, AL_OFF + r * 272 + q * 8, v);
    }
    __syncthreads();

    int wm = wid >> 2, wn = wid & 3;
    int grp = lane >> 3, lr = lane & 7;
    unsigned aA = base + AH_OFF + ((wm * 32 + (grp & 1) * 8 + lr) * 136 + (grp >> 1) * 8) * 2;
    unsigned bB = base + WH_OFF + ((wn * 32 + (grp >> 1) * 8 + lr) * 136 + (grp & 1) * 8) * 2;

    float acc[2][4][4];
#pragma unroll
    for (int a = 0; a < 2; a++)
#pragma unroll
        for (int b = 0; b < 4; b++)
#pragma unroll
            for (int c = 0; c < 4; c++) acc[a][b][c] = 0.f;

#pragma unroll 2
    for (int ks = 0; ks < 8; ks++) {
        unsigned ah0[4], ah1[4], al0[4], al1[4];
        ldsm4(ah0, aA + ks * 32);
        ldsm4(ah1, aA + 4352 + ks * 32);
        ldsm4(al0, aA + 17408 + ks * 32);
        ldsm4(al1, aA + 17408 + 4352 + ks * 32);
#pragma unroll
        for (int nb2 = 0; nb2 < 2; nb2++) {
            unsigned bh[4], bl[4];
            ldsm4(bh, bB + nb2 * 4352 + ks * 32);
            ldsm4(bl, bB + 34816 + nb2 * 4352 + ks * 32);
            mma16816(acc[0][2 * nb2],     ah0, bh[0], bh[1]);
            mma16816(acc[0][2 * nb2 + 1], ah0, bh[2], bh[3]);
            mma16816(acc[1][2 * nb2],     ah1, bh[0], bh[1]);
            mma16816(acc[1][2 * nb2 + 1], ah1, bh[2], bh[3]);
            mma16816(acc[0][2 * nb2],     ah0, bl[0], bl[1]);
            mma16816(acc[0][2 * nb2 + 1], ah0, bl[2], bl[3]);
            mma16816(acc[1][2 * nb2],     ah1, bl[0], bl[1]);
            mma16816(acc[1][2 * nb2 + 1], ah1, bl[2], bl[3]);
            mma16816(acc[0][2 * nb2],     al0, bh[0], bh[1]);
            mma16816(acc[0][2 * nb2 + 1], al0, bh[2], bh[3]);
            mma16816(acc[1][2 * nb2],     al1, bh[0], bh[1]);
            mma16816(acc[1][2 * nb2 + 1], al1, bh[2], bh[3]);
        }
    }
    __syncthreads();

    // stage accumulators to smem [64][132] f32 (overwrites A region), coalesced writeout
    float* stg = (float*)p;
#pragma unroll
    for (int mf = 0; mf < 2; mf++)
#pragma unroll
        for (int nb = 0; nb < 4; nb++)
#pragma unroll
            for (int i = 0; i < 4; i++) {
                int row = wm * 32 + mf * 16 + (lane >> 2) + (i >> 1) * 8;
                int col = wn * 32 + nb * 8 + (lane & 3) * 2 + (i & 1);
                stg[row * 132 + col] = acc[mf][nb][i];
            }
    __syncthreads();
#pragma unroll
    for (int i = 0; i < 8; i++) {
        int fi = tid + i * 256;
        int r = fi >> 5, q = fi & 31;
        int rr = r0 + r;
        if (rr < n) {
            float4 v;
            v.x = stg[r * 132 + q * 4 + 0]; v.y = stg[r * 132 + q * 4 + 1];
            v.z = stg[r * 132 + q * 4 + 2]; v.w = stg[r * 132 + q * 4 + 3];
            *(float4*)(Y + (size_t)rr * yLd + blockIdx.y * 128 + q * 4) = v;
        }
    }
}

// ---------------- aggregate: warp per node, CSR gather (all dinv scaling here) ----------------
// agg[c] = dinv[c] * (dinv[c]*hw[c] + sum_{r in in(c)} dinv[r]*hw[r])
__global__ __launch_bounds__(256)
void k_aggregate(const float* __restrict__ Z, float* __restrict__ agg, int n) {
    int gw = (blockIdx.x * 256 + threadIdx.x) >> 5;
    int q = threadIdx.x & 31;
    if (gw >= n) return;
    int s = g_off[gw], e = g_off[gw + 1];
    const float4* Z4 = (const float4*)Z;
    float dvc = g_dinv[gw];
    float4 a = Z4[(size_t)gw * 32 + q];
    float4 acc;
    acc.x = dvc * a.x; acc.y = dvc * a.y; acc.z = dvc * a.z; acc.w = dvc * a.w;
    for (int i = s; i < e; i++) {
        int r = g_csr[i];
        float dr = g_dinv[r];
        float4 z = Z4[(size_t)r * 32 + q];
        acc.x += dr * z.x; acc.y += dr * z.y; acc.z += dr * z.z; acc.w += dr * z.w;
    }
    acc.x *= dvc; acc.y *= dvc; acc.z *= dvc; acc.w *= dvc;
    ((float4*)agg)[(size_t)gw * 32 + q] = acc;
}

// ---------------- edge kernel: gather+relu (factorized L1) -> HMMA L2 -> L3+sigmoid ----
__global__ __launch_bounds__(256)
void k_edge_hmma(const float* __restrict__ P,
                 const int* __restrict__ row, const int* __restrict__ col,
                 const float* __restrict__ be, const float* __restrict__ bc1,
                 const float* __restrict__ Wc2, const float* __restrict__ bc2,
                 float* __restrict__ out, int E) {
    extern __shared__ char p[];
    unsigned base = smem_u32(p);
    int*   sr   = (int*)(p + ESR_OFF);
    int*   sc   = (int*)(p + ESC_OFF);
    float* wdf  = (float*)(p + EWD_OFF);
    float* sbc1 = (float*)(p + EBC_OFF);
    float* eacc = (float*)(p + EAC_OFF);
    int tid = threadIdx.x, wid = tid >> 5, lane = tid & 31;
    int e0 = blockIdx.x * 128;

    if (tid < 128) {
        int e = e0 + tid; if (e >= E) e = E - 1;
        sr[tid] = row[e]; sc[tid] = col[e];
        eacc[tid] = 0.f;
    }
    if (tid < 64) {
        wdf[tid]  = Wc2[tid * 2 + 1] - Wc2[tid * 2];
        sbc1[tid] = bc1[tid];
    }
    {   // stage Wc1t [64][136] h/l
        const float4* sH = (const float4*)g_wc1t_h;
        const float4* sL = (const float4*)g_wc1t_l;
#pragma unroll
        for (int i = 0; i < 4; i++) {
            int idx = tid + i * 256;                 // 0..1023
            int r = idx >> 4, seg = idx & 15;
            *(float4*)(p + EWH_OFF + r * 272 + seg * 16) = sH[idx];
            *(float4*)(p + EWL_OFF + r * 272 + seg * 16) = sL[idx];
        }
    }
    __syncthreads();   // sr/sc + eacc ready

    const float4* P4 = (const float4*)P;
#pragma unroll
    for (int i = 0; i < 16; i++) {
        int fi = tid + i * 256;
        int e = fi >> 5, q = fi & 31;
        float4 v = P4[(size_t)sr[e] * 64 + q];
        float4 u = P4[(size_t)sc[e] * 64 + 32 + q];
        float4 b = *(const float4*)(be + q * 4);
        v.x = fmaxf(v.x + u.x + b.x, 0.f);
        v.y = fmaxf(v.y + u.y + b.y, 0.f);
        v.z = fmaxf(v.z + u.z + b.z, 0.f);
        v.w = fmaxf(v.w + u.w + b.w, 0.f);
        split_store(p, EAH_OFF + e * 272 + q * 8, EAL_OFF + e * 272 + q * 8, v);
    }
    __syncthreads();

    int wm = wid >> 1, wn = wid & 1;
    int grp = lane >> 3, lr = lane & 7;
    unsigned aA = base + EAH_OFF + ((wm * 32 + (grp & 1) * 8 + lr) * 136 + (grp >> 1) * 8) * 2;
    unsigned bB = base + EWH_OFF + ((wn * 32 + (grp >> 1) * 8 + lr) * 136 + (grp & 1) * 8) * 2;

    float acc[2][4][4];
#pragma unroll
    for (int a = 0; a < 2; a++)
#pragma unroll
        for (int b = 0; b < 4; b++)
#pragma unroll
            for (int c = 0; c < 4; c++) acc[a][b][c] = 0.f;

#pragma unroll 2
    for (int ks = 0; ks < 8; ks++) {
        unsigned ah0[4], ah1[4], al0[4], al1[4];
        ldsm4(ah0, aA + ks * 32);
        ldsm4(ah1, aA + 4352 + ks * 32);
        ldsm4(al0, aA + 34816 + ks * 32);
        ldsm4(al1, aA + 34816 + 4352 + ks * 32);
#pragma unroll
        for (int nb2 = 0; nb2 < 2; nb2++) {
            unsigned bh[4], bl[4];
            ldsm4(bh, bB + nb2 * 4352 + ks * 32);
            ldsm4(bl, bB + 17408 + nb2 * 4352 + ks * 32);
            mma16816(acc[0][2 * nb2],     ah0, bh[0], bh[1]);
            mma16816(acc[0][2 * nb2 + 1], ah0, bh[2], bh[3]);
            mma16816(acc[1][2 * nb2],     ah1, bh[0], bh[1]);
            mma16816(acc[1][2 * nb2 + 1], ah1, bh[2], bh[3]);
            mma16816(acc[0][2 * nb2],     ah0, bl[0], bl[1]);
            mma16816(acc[0][2 * nb2 + 1], ah0, bl[2], bl[3]);
            mma16816(acc[1][2 * nb2],     ah1, bl[0], bl[1]);
            mma16816(acc[1][2 * nb2 + 1], ah1, bl[2], bl[3]);
            mma16816(acc[0][2 * nb2],     al0, bh[0], bh[1]);
            mma16816(acc[0][2 * nb2 + 1], al0, bh[2], bh[3]);
            mma16816(acc[1][2 * nb2],     al1, bh[0], bh[1]);
            mma16816(acc[1][2 * nb2 + 1], al1, bh[2], bh[3]);
        }
    }

    // epilogue: h2 = relu(acc + bc1); partial dot with wdf; reduce lanes + warps
#pragma unroll
    for (int mf = 0; mf < 2; mf++) {
        float pr = 0.f, pr8 = 0.f;
#pragma unroll
        for (int nb = 0; nb < 4; nb++) {
            int c = wn * 32 + nb * 8 + (lane & 3) * 2;
            pr  += fmaxf(acc[mf][nb][0] + sbc1[c],     0.f) * wdf[c]
                 + fmaxf(acc[mf][nb][1] + sbc1[c + 1], 0.f) * wdf[c + 1];
            pr8 += fmaxf(acc[mf][nb][2] + sbc1[c],     0.f) * wdf[c]
                 + fmaxf(acc[mf][nb][3] + sbc1[c + 1], 0.f) * wdf[c + 1];
        }
#pragma unroll
        for (int o = 1; o <= 2; o <<= 1) {
            pr  += __shfl_xor_sync(0xFFFFFFFFu, pr, o);
            pr8 += __shfl_xor_sync(0xFFFFFFFFu, pr8, o);
        }
        if ((lane & 3) == 0) {
            int rl = wm * 32 + mf * 16 + (lane >> 2);
            atomicAdd(&eacc[rl], pr);
            atomicAdd(&eacc[rl + 8], pr8);
        }
    }
    __syncthreads();
    if (tid < 128) {
        int e = e0 + tid;
        float bd = bc2[1] - bc2[0];
        if (e < E) out[e] = 1.f / (1.f + expf(-(eacc[tid] + bd)));
    }
}

extern "C" void kernel_launch(void* const* d_in, const int* in_sizes, int n_in,
                              void* d_out, int out_size) {
    const float* x   = (const float*)d_in[0];
    const int*   ei  = (const int*)d_in[1];
    const float* W1  = (const float*)d_in[2];
    const float* b1  = (const float*)d_in[3];
    const float* W2  = (const float*)d_in[4];
    const float* b2  = (const float*)d_in[5];
    const float* We  = (const float*)d_in[6];
    const float* be  = (const float*)d_in[7];
    const float* Wc1 = (const float*)d_in[8];
    const float* bc1 = (const float*)d_in[9];
    const float* Wc2 = (const float*)d_in[10];
    const float* bc2 = (const float*)d_in[11];
    float* out = (float*)d_out;

    int n = in_sizes[0] / HID;          // 100000
    int E = in_sizes[1] / 2;            // 500000
    const int* row = ei;
    const int* col = ei + E;

    float *buf0, *buf1, *buf2, *bufP;
    cudaGetSymbolAddress((void**)&buf0, g_buf0);
    cudaGetSymbolAddress((void**)&buf1, g_buf1);
    cudaGetSymbolAddress((void**)&buf2, g_buf2);
    cudaGetSymbolAddress((void**)&bufP, g_bufP);
    __nv_bfloat16 *w1h, *w1l, *w2h, *w2l, *weh, *wel;
    cudaGetSymbolAddress((void**)&w1h, g_w1t_h); cudaGetSymbolAddress((void**)&w1l, g_w1t_l);
    cudaGetSymbolAddress((void**)&w2h, g_w2t_h); cudaGetSymbolAddress((void**)&w2l, g_w2t_l);
    cudaGetSymbolAddress((void**)&weh, g_wet_h); cudaGetSymbolAddress((void**)&wel, g_wet_l);

    static cudaStream_t sA = nullptr;
    static cudaEvent_t evFork = nullptr, evJoin = nullptr;
    static int inited = 0;
    if (!inited) {
        cudaFuncSetAttribute(k_gemm_hmma, cudaFuncAttributeMaxDynamicSharedMemorySize, GEMM_SMEM);
        cudaFuncSetAttribute(k_edge_hmma, cudaFuncAttributeMaxDynamicSharedMemorySize, EDGE_SMEM);
        cudaStreamCreateWithFlags(&sA, cudaStreamNonBlocking);
        cudaEventCreateWithFlags(&evFork, cudaEventDisableTiming);
        cudaEventCreateWithFlags(&evJoin, cudaEventDisableTiming);
        inited = 1;
    }

    dim3 b256(256);
    int gEdge = (E + 255) / 256;
    int gScanB = (n + 255) / 256;      // 391
    int gG    = (n + 63) / 64;
    int gAgg  = (n + 7) / 8;           // warp per node, 8 warps/block
    int gM    = (E + 127) / 128;

    // prep first (conv1 GEMM needs weights), then fork CSR build to side stream
    k_prep<<<288, b256>>>(W1, W2, We, Wc1);
    cudaEventRecord(evFork, 0);
    cudaStreamWaitEvent(sA, evFork, 0);
    k_deg_count<<<gEdge, b256, 0, sA>>>(col, E);
    k_scan1<<<gScanB, b256, 0, sA>>>(n);
    k_scan2<<<1, 512, 0, sA>>>(gScanB);
    k_scan3<<<gScanB, b256, 0, sA>>>(n, E);
    k_fill<<<gEdge, b256, 0, sA>>>(row, col, E);
    cudaEventRecord(evJoin, sA);

    // conv1 GEMM (unscaled hw1) runs concurrently with CSR build
    k_gemm_hmma<<<dim3(gG, 1), b256, GEMM_SMEM>>>(x, nullptr, 0, w1h, w1l, buf0, HID, n);
    cudaStreamWaitEvent(0, evJoin, 0);
    k_aggregate<<<gAgg, b256>>>(buf0, buf1, n);

    // conv2: A = relu(agg1+b1); hw2 (buf2); agg2 (buf0)
    k_gemm_hmma<<<dim3(gG, 1), b256, GEMM_SMEM>>>(buf1, b1, 1, w2h, w2l, buf2, HID, n);
    k_aggregate<<<gAgg, b256>>>(buf2, buf0, n);

    // P[N,256] = (agg2+b2) @ [We_top | We_bot]  (grid.y selects half)
    k_gemm_hmma<<<dim3(gG, 2), b256, GEMM_SMEM>>>(buf0, b2, 2, weh, wel, bufP, 256, n);

    // edge: gather-add-relu + HMMA layer2 + layer3 + sigmoid
    k_edge_hmma<<<gM, b256, EDGE_SMEM>>>(bufP, row, col, be, bc1, Wc2, bc2, out, E);
}